// round 2
// baseline (speedup 1.0000x reference)
#include <cuda_runtime.h>
#include <cuda_bf16.h>
#include <math.h>

// Problem constants
#define Bz      8192
#define NNETS   30
#define NNODES  20
#define NOUT    10
#define DOUT    16
#define INDIM   784
#define NCOL    600          // NNETS*NNODES
#define NPAD    640          // padded to multiple of 64

// Scratch (device globals; zero-initialized .bss — pad columns of W1p stay 0)
__device__ float g_W1p[INDIM * NPAD];     // [k][j] j = n*20+o, cols 600..639 zero
__device__ float g_b1p[NPAD];
__device__ float g_h1[Bz * NPAD];         // relu(x@W1+b1)
__device__ float g_u[Bz * NCOL];          // squashed layer-2 output

// ---------------------------------------------------------------------------
// K0: pack W1 into [784, 640] row-major, pad bias
// ---------------------------------------------------------------------------
__global__ void pack_kernel(const float* __restrict__ W1, const float* __restrict__ b1) {
    int idx = blockIdx.x * blockDim.x + threadIdx.x;
    if (idx < INDIM * NCOL) {
        int k = idx / NCOL;
        int j = idx % NCOL;
        int n = j / NNODES;
        int o = j % NNODES;
        g_W1p[k * NPAD + j] = W1[n * (INDIM * NNODES) + k * NNODES + o];
    }
    if (idx < NPAD) {
        g_b1p[idx] = (idx < NCOL) ? b1[idx] : 0.f;
    }
}

// ---------------------------------------------------------------------------
// K1: C[8192,640] = relu(A[8192,784] @ W1p[784,640] + b1p)
// 128x64 tile, BK=16, 256 threads, 8x4 microkernel (unchanged from R1)
// ---------------------------------------------------------------------------
__global__ __launch_bounds__(256) void gemm1_kernel(const float* __restrict__ A) {
    __shared__ float As[16][132];
    __shared__ float Bs[16][64];

    const int tid = threadIdx.x;
    const int bm  = blockIdx.x & 63;
    const int bn  = blockIdx.x >> 6;
    const int tx  = tid & 15;
    const int ty  = tid >> 4;

    const int arow  = tid >> 2;
    const int acol4 = (tid & 3) * 4;
    const int brow  = tid >> 4;
    const int bcol4 = (tid & 15) * 4;

    const float* Ap = A + (size_t)(bm * 128 + arow) * INDIM + acol4;
    const float* Bp = g_W1p + (size_t)brow * NPAD + bn * 64 + bcol4;

    float acc[8][4];
    #pragma unroll
    for (int i = 0; i < 8; i++)
        #pragma unroll
        for (int j = 0; j < 4; j++) acc[i][j] = 0.f;

    for (int kt = 0; kt < INDIM; kt += 16) {
        float4 a0 = *(const float4*)(Ap + kt);
        float4 a1 = *(const float4*)(Ap + (size_t)64 * INDIM + kt);
        float4 b0 = *(const float4*)(Bp + (size_t)kt * NPAD);

        As[acol4 + 0][arow] = a0.x;
        As[acol4 + 1][arow] = a0.y;
        As[acol4 + 2][arow] = a0.z;
        As[acol4 + 3][arow] = a0.w;
        As[acol4 + 0][arow + 64] = a1.x;
        As[acol4 + 1][arow + 64] = a1.y;
        As[acol4 + 2][arow + 64] = a1.z;
        As[acol4 + 3][arow + 64] = a1.w;
        *(float4*)&Bs[brow][bcol4] = b0;
        __syncthreads();

        #pragma unroll
        for (int k = 0; k < 16; k++) {
            float4 av0 = *(const float4*)&As[k][ty * 8];
            float4 av1 = *(const float4*)&As[k][ty * 8 + 4];
            float4 bv  = *(const float4*)&Bs[k][tx * 4];
            float a[8] = {av0.x, av0.y, av0.z, av0.w, av1.x, av1.y, av1.z, av1.w};
            float b[4] = {bv.x, bv.y, bv.z, bv.w};
            #pragma unroll
            for (int i = 0; i < 8; i++)
                #pragma unroll
                for (int j = 0; j < 4; j++)
                    acc[i][j] = fmaf(a[i], b[j], acc[i][j]);
        }
        __syncthreads();
    }

    const int colbase = bn * 64 + tx * 4;
    float4 bias = *(const float4*)&g_b1p[colbase];
    #pragma unroll
    for (int i = 0; i < 8; i++) {
        int row = bm * 128 + ty * 8 + i;
        float4 v;
        v.x = fmaxf(acc[i][0] + bias.x, 0.f);
        v.y = fmaxf(acc[i][1] + bias.y, 0.f);
        v.z = fmaxf(acc[i][2] + bias.z, 0.f);
        v.w = fmaxf(acc[i][3] + bias.w, 0.f);
        *(float4*)&g_h1[(size_t)row * NPAD + colbase] = v;
    }
}

// ---------------------------------------------------------------------------
// K2: per (b, net): h2 = relu(h1 @ W2[n] + b2[n]); u = squash(h2)
// ---------------------------------------------------------------------------
__global__ __launch_bounds__(256) void layer2_kernel(const float* __restrict__ W2,
                                                     const float* __restrict__ b2) {
    int warp = (blockIdx.x * blockDim.x + threadIdx.x) >> 5;
    int lane = threadIdx.x & 31;
    if (warp >= Bz * NNETS) return;
    int b = warp / NNETS;
    int n = warp % NNETS;

    const float* hrow = g_h1 + (size_t)b * NPAD + n * NNODES;
    float hv = (lane < NNODES) ? hrow[lane] : 0.f;

    int e = (lane < NNODES) ? lane : 0;
    const float* w = W2 + n * (NNODES * NNODES) + e;
    float acc = 0.f;
    #pragma unroll
    for (int d = 0; d < NNODES; d++) {
        float hd = __shfl_sync(0xffffffffu, hv, d);
        acc = fmaf(hd, w[d * NNODES], acc);
    }

    float h2 = 0.f;
    if (lane < NNODES) h2 = fmaxf(acc + b2[n * NNODES + lane], 0.f);

    float sq = h2 * h2;
    #pragma unroll
    for (int off = 16; off; off >>= 1) sq += __shfl_xor_sync(0xffffffffu, sq, off);

    float factor = sqrtf(sq) / (1.f + sq);
    if (lane < NNODES) g_u[(size_t)b * NCOL + n * NNODES + lane] = h2 * factor;
}

// ---------------------------------------------------------------------------
// K3 (REWRITTEN): priors + 3 routing iterations, priors in REGISTERS.
// 160 threads = (o,k) pairs; block handles MB=4 batch rows.
// Each thread holds pri[30][4] in registers; k-reductions via 16-lane shuffles.
// ---------------------------------------------------------------------------
__device__ __forceinline__ float red16(float x) {
    x += __shfl_xor_sync(0xffffffffu, x, 1);
    x += __shfl_xor_sync(0xffffffffu, x, 2);
    x += __shfl_xor_sync(0xffffffffu, x, 4);
    x += __shfl_xor_sync(0xffffffffu, x, 8);
    return x;
}

__global__ __launch_bounds__(160, 2) void routing_kernel(const float* __restrict__ rw,
                                                         float* __restrict__ out) {
    __shared__ float us[4 * NCOL];      // u rows, [mb][600]
    __shared__ float lg[4 * 300];       // logits [mb][o*30+n]
    __shared__ float pb[4 * 300];       // probs  [mb][o*30+n]

    const int tid = threadIdx.x;
    const int o   = tid >> 4;           // 0..9
    const int k   = tid & 15;           // 0..15
    const int b0  = blockIdx.x * 4;

    // stage u (float4) and zero logits
    {
        const float4* gu = (const float4*)(g_u + (size_t)b0 * NCOL);
        for (int i = tid; i < NCOL; i += 160) ((float4*)us)[i] = gu[i];
        for (int i = tid; i < 4 * 300; i += 160) lg[i] = 0.f;
    }
    __syncthreads();

    // ---- priors into registers: pri[n][mb] = sum_d u[mb][n,d] * rw[o,n,d,k] ----
    float pri[NNETS][4];
    {
        const float* rwp = rw + (size_t)o * (NNETS * NNODES * DOUT) + k;
        #pragma unroll
        for (int n = 0; n < NNETS; n++) {
            float a0 = 0.f, a1 = 0.f, a2 = 0.f, a3 = 0.f;
            #pragma unroll
            for (int dq = 0; dq < 5; dq++) {
                float4 u0 = *(const float4*)&us[0 * NCOL + n * 20 + dq * 4];
                float4 u1 = *(const float4*)&us[1 * NCOL + n * 20 + dq * 4];
                float4 u2 = *(const float4*)&us[2 * NCOL + n * 20 + dq * 4];
                float4 u3 = *(const float4*)&us[3 * NCOL + n * 20 + dq * 4];
                #pragma unroll
                for (int j = 0; j < 4; j++) {
                    float w = rwp[(n * 20 + dq * 4 + j) * 16];
                    a0 = fmaf(w, (&u0.x)[j], a0);
                    a1 = fmaf(w, (&u1.x)[j], a1);
                    a2 = fmaf(w, (&u2.x)[j], a2);
                    a3 = fmaf(w, (&u3.x)[j], a3);
                }
            }
            pri[n][0] = a0; pri[n][1] = a1; pri[n][2] = a2; pri[n][3] = a3;
        }
    }

    // ---- 3 routing iterations ----
    float v[4];
    for (int it = 0; it < 3; it++) {
        __syncthreads();
        // softmax over o, per (mb, n): 120 threads
        if (tid < 120) {
            int mb = tid / NNETS, n = tid % NNETS;
            float* L = lg + mb * 300 + n;
            float m = L[0];
            #pragma unroll
            for (int oo = 1; oo < NOUT; oo++) m = fmaxf(m, L[oo * 30]);
            float e[NOUT];
            float ss = 0.f;
            #pragma unroll
            for (int oo = 0; oo < NOUT; oo++) { e[oo] = __expf(L[oo * 30] - m); ss += e[oo]; }
            float inv = 1.f / ss;
            float* P = pb + mb * 300 + n;
            #pragma unroll
            for (int oo = 0; oo < NOUT; oo++) P[oo * 30] = e[oo] * inv;
        }
        __syncthreads();

        // s[o,k] = sum_n probs[o,n] * pri[n];  v = squash(s)
        #pragma unroll
        for (int mb = 0; mb < 4; mb++) {
            const float* P = pb + mb * 300 + o * 30;
            float s = 0.f;
            #pragma unroll
            for (int n = 0; n < NNETS; n++) s = fmaf(P[n], pri[n][mb], s);
            float sq = red16(s * s);
            float f = sqrtf(sq) / (1.f + sq);
            v[mb] = s * f;
        }

        // logits += sum_k pri * v   (skip last iter)
        if (it < 2) {
            #pragma unroll
            for (int mb = 0; mb < 4; mb++) {
                #pragma unroll
                for (int n = 0; n < NNETS; n++) {
                    float t = red16(pri[n][mb] * v[mb]);
                    if (k == (n & 15)) lg[mb * 300 + o * 30 + n] += t;
                }
            }
        }
    }

    // write v: out[b, o, k]
    #pragma unroll
    for (int mb = 0; mb < 4; mb++)
        out[(size_t)(b0 + mb) * (NOUT * DOUT) + tid] = v[mb];
}

// ---------------------------------------------------------------------------
extern "C" void kernel_launch(void* const* d_in, const int* in_sizes, int n_in,
                              void* d_out, int out_size) {
    const float* x  = (const float*)d_in[0];
    const float* W1 = (const float*)d_in[1];
    const float* b1 = (const float*)d_in[2];
    const float* W2 = (const float*)d_in[3];
    const float* b2 = (const float*)d_in[4];
    const float* rw = (const float*)d_in[5];
    float* out = (float*)d_out;

    (void)in_sizes; (void)n_in; (void)out_size;

    pack_kernel<<<(INDIM * NCOL + 255) / 256, 256>>>(W1, b1);
    gemm1_kernel<<<64 * 10, 256>>>(x);
    layer2_kernel<<<(Bz * NNETS) / 8, 256>>>(W2, b2);
    routing_kernel<<<Bz / 4, 160>>>(rw, out);
}

// round 3
// speedup vs baseline: 1.2249x; 1.2249x over previous
#include <cuda_runtime.h>
#include <cuda_bf16.h>
#include <math.h>

// Problem constants
#define Bz      8192
#define NNETS   30
#define NNODES  20
#define NOUT    10
#define DOUT    16
#define INDIM   784
#define NCOL    600          // NNETS*NNODES
#define NPAD    640          // padded to multiple of 64

// Scratch
__device__ float g_W1p[INDIM * NPAD];
__device__ float g_b1p[NPAD];
__device__ float g_h1[Bz * NPAD];
__device__ float g_u[Bz * NCOL];

// ---------------------------------------------------------------------------
// K0: pack W1 into [784, 640] row-major, pad bias
// ---------------------------------------------------------------------------
__global__ void pack_kernel(const float* __restrict__ W1, const float* __restrict__ b1) {
    int idx = blockIdx.x * blockDim.x + threadIdx.x;
    if (idx < INDIM * NCOL) {
        int k = idx / NCOL;
        int j = idx % NCOL;
        int n = j / NNODES;
        int o = j % NNODES;
        g_W1p[k * NPAD + j] = W1[n * (INDIM * NNODES) + k * NNODES + o];
    }
    if (idx < NPAD) {
        g_b1p[idx] = (idx < NCOL) ? b1[idx] : 0.f;
    }
}

// ---------------------------------------------------------------------------
// K1: C[8192,640] = relu(A @ W1p + b1p); 128x64 tile, BK=16, register-prefetch
// software pipeline so LDG of tile t+1 overlaps FMA of tile t.
// ---------------------------------------------------------------------------
__global__ __launch_bounds__(256) void gemm1_kernel(const float* __restrict__ A) {
    __shared__ float As[16][132];
    __shared__ float Bs[16][64];

    const int tid = threadIdx.x;
    const int bm  = blockIdx.x & 63;
    const int bn  = blockIdx.x >> 6;
    const int tx  = tid & 15;
    const int ty  = tid >> 4;

    const int arow  = tid >> 2;
    const int acol4 = (tid & 3) * 4;
    const int brow  = tid >> 4;
    const int bcol4 = (tid & 15) * 4;

    const float* Ap = A + (size_t)(bm * 128 + arow) * INDIM + acol4;
    const float* Bp = g_W1p + (size_t)brow * NPAD + bn * 64 + bcol4;

    float acc[8][4];
    #pragma unroll
    for (int i = 0; i < 8; i++)
        #pragma unroll
        for (int j = 0; j < 4; j++) acc[i][j] = 0.f;

    float4 a0 = *(const float4*)(Ap);
    float4 a1 = *(const float4*)(Ap + (size_t)64 * INDIM);
    float4 b0 = *(const float4*)(Bp);

    for (int kt = 0; kt < INDIM; kt += 16) {
        As[acol4 + 0][arow] = a0.x;
        As[acol4 + 1][arow] = a0.y;
        As[acol4 + 2][arow] = a0.z;
        As[acol4 + 3][arow] = a0.w;
        As[acol4 + 0][arow + 64] = a1.x;
        As[acol4 + 1][arow + 64] = a1.y;
        As[acol4 + 2][arow + 64] = a1.z;
        As[acol4 + 3][arow + 64] = a1.w;
        *(float4*)&Bs[brow][bcol4] = b0;
        __syncthreads();

        if (kt + 16 < INDIM) {   // prefetch next tile while computing this one
            a0 = *(const float4*)(Ap + kt + 16);
            a1 = *(const float4*)(Ap + (size_t)64 * INDIM + kt + 16);
            b0 = *(const float4*)(Bp + (size_t)(kt + 16) * NPAD);
        }

        #pragma unroll
        for (int k = 0; k < 16; k++) {
            float4 av0 = *(const float4*)&As[k][ty * 8];
            float4 av1 = *(const float4*)&As[k][ty * 8 + 4];
            float4 bv  = *(const float4*)&Bs[k][tx * 4];
            float a[8] = {av0.x, av0.y, av0.z, av0.w, av1.x, av1.y, av1.z, av1.w};
            float b[4] = {bv.x, bv.y, bv.z, bv.w};
            #pragma unroll
            for (int i = 0; i < 8; i++)
                #pragma unroll
                for (int j = 0; j < 4; j++)
                    acc[i][j] = fmaf(a[i], b[j], acc[i][j]);
        }
        __syncthreads();
    }

    const int colbase = bn * 64 + tx * 4;
    float4 bias = *(const float4*)&g_b1p[colbase];
    #pragma unroll
    for (int i = 0; i < 8; i++) {
        int row = bm * 128 + ty * 8 + i;
        float4 v;
        v.x = fmaxf(acc[i][0] + bias.x, 0.f);
        v.y = fmaxf(acc[i][1] + bias.y, 0.f);
        v.z = fmaxf(acc[i][2] + bias.z, 0.f);
        v.w = fmaxf(acc[i][3] + bias.w, 0.f);
        *(float4*)&g_h1[(size_t)row * NPAD + colbase] = v;
    }
}

// ---------------------------------------------------------------------------
// K2: per (b, net): h2 = relu(h1 @ W2[n] + b2[n]); u = squash(h2)
// ---------------------------------------------------------------------------
__global__ __launch_bounds__(256) void layer2_kernel(const float* __restrict__ W2,
                                                     const float* __restrict__ b2) {
    int warp = (blockIdx.x * blockDim.x + threadIdx.x) >> 5;
    int lane = threadIdx.x & 31;
    if (warp >= Bz * NNETS) return;
    int b = warp / NNETS;
    int n = warp % NNETS;

    const float* hrow = g_h1 + (size_t)b * NPAD + n * NNODES;
    float hv = (lane < NNODES) ? hrow[lane] : 0.f;

    int e = (lane < NNODES) ? lane : 0;
    const float* w = W2 + n * (NNODES * NNODES) + e;
    float acc = 0.f;
    #pragma unroll
    for (int d = 0; d < NNODES; d++) {
        float hd = __shfl_sync(0xffffffffu, hv, d);
        acc = fmaf(hd, w[d * NNODES], acc);
    }

    float h2 = 0.f;
    if (lane < NNODES) h2 = fmaxf(acc + b2[n * NNODES + lane], 0.f);

    float sq = h2 * h2;
    #pragma unroll
    for (int off = 16; off; off >>= 1) sq += __shfl_xor_sync(0xffffffffu, sq, off);

    float factor = sqrtf(sq) / (1.f + sq);
    if (lane < NNODES) g_u[(size_t)b * NCOL + n * NNODES + lane] = h2 * factor;
}

// ---------------------------------------------------------------------------
// K3 v3: smem priors with CONFLICT-FREE k-major layout.
//   pri index: P(k, mb, pair) = k*KSTR + mb*304 + pair,  KSTR = 1217 (== 1 mod 32)
//   -> lanes differing in k hit distinct banks; pair-major phases are consecutive.
// 320 threads, MB=4 batch rows per block.
// ---------------------------------------------------------------------------
#define KSTR 1217
#define RT_THREADS 320
// floats: us 2400 | pri 16*1217=19472 | lg 1200 | pb 1200 | vv 640
#define RT_SMEM_FLOATS (2400 + 16*KSTR + 1200 + 1200 + 640)
#define RT_SMEM_BYTES  (RT_SMEM_FLOATS * 4)

__device__ __forceinline__ float red16(float x) {
    x += __shfl_xor_sync(0xffffffffu, x, 1);
    x += __shfl_xor_sync(0xffffffffu, x, 2);
    x += __shfl_xor_sync(0xffffffffu, x, 4);
    x += __shfl_xor_sync(0xffffffffu, x, 8);
    return x;
}

__global__ __launch_bounds__(RT_THREADS, 2) void routing_kernel(const float* __restrict__ rw,
                                                                float* __restrict__ out) {
    extern __shared__ float sm[];
    float* us  = sm;                 // [4][600]
    float* pri = us  + 2400;         // k-major padded
    float* lg  = pri + 16 * KSTR;    // [4][300]
    float* pb  = lg  + 1200;         // [4][300]
    float* vv  = pb  + 1200;         // [4][160]

    const int tid = threadIdx.x;
    const int b0  = blockIdx.x * 4;

    // stage u rows (float4), zero logits
    {
        const float4* gu = (const float4*)(g_u + (size_t)b0 * NCOL);
        for (int i = tid; i < 600; i += RT_THREADS) ((float4*)us)[i] = gu[i];
        for (int i = tid; i < 1200; i += RT_THREADS) lg[i] = 0.f;
    }
    __syncthreads();

    // ---- priors: thread (k, pr0) handles pairs pr0, pr0+20, ... ----
    {
        const int k   = tid & 15;
        const int pr0 = tid >> 4;               // 0..19
        #pragma unroll
        for (int pg = 0; pg < 300; pg += 20) {
            const int pair = pg + pr0;          // = o*30 + n
            const int n = pair % NNETS;
            const float* rwp = rw + (size_t)pair * 320 + k;   // (pair*20+d)*16+k
            const float* un  = us + n * NNODES;
            float a0 = 0.f, a1 = 0.f, a2 = 0.f, a3 = 0.f;
            #pragma unroll
            for (int d = 0; d < NNODES; d++) {
                float w = rwp[d * 16];
                a0 = fmaf(w, un[d],            a0);
                a1 = fmaf(w, un[600 + d],      a1);
                a2 = fmaf(w, un[1200 + d],     a2);
                a3 = fmaf(w, un[1800 + d],     a3);
            }
            float* P = pri + k * KSTR + pair;
            P[0]       = a0;
            P[304]     = a1;
            P[608]     = a2;
            P[912]     = a3;
        }
    }

    // ---- 3 routing iterations ----
    for (int it = 0; it < 3; it++) {
        __syncthreads();
        // (a) softmax over o per (mb, n)
        if (tid < 120) {
            int mb = tid / NNETS, n = tid % NNETS;
            float* L = lg + mb * 300 + n;
            float m = L[0];
            #pragma unroll
            for (int oo = 1; oo < NOUT; oo++) m = fmaxf(m, L[oo * 30]);
            float e[NOUT];
            float ss = 0.f;
            #pragma unroll
            for (int oo = 0; oo < NOUT; oo++) { e[oo] = __expf(L[oo * 30] - m); ss += e[oo]; }
            float inv = 1.f / ss;
            float* P = pb + mb * 300 + n;
            #pragma unroll
            for (int oo = 0; oo < NOUT; oo++) P[oo * 30] = e[oo] * inv;
        }
        __syncthreads();

        // (b,c) s[mb,o,k] = sum_n pb * pri ; v = squash(s) ; 640 items in 2 passes
        #pragma unroll
        for (int pass = 0; pass < 2; pass++) {
            int idx = tid + pass * RT_THREADS;     // < 640
            int mb = idx / 160;
            int r  = idx % 160;                    // o*16 + k
            int o  = r >> 4;
            int k  = idx & 15;                     // == lane&15 (320 mult of 32)
            const float* P  = pb  + mb * 300 + o * 30;
            const float* PR = pri + k * KSTR + mb * 304 + o * 30;
            float s = 0.f;
            #pragma unroll
            for (int n = 0; n < NNETS; n++) s = fmaf(P[n], PR[n], s);
            float sq = red16(s * s);
            float f = sqrtf(sq) / (1.f + sq);
            vv[mb * 160 + r] = s * f;
        }

        // (d) logits += sum_k pri * v  (skip last iteration)
        if (it < 2) {
            __syncthreads();
            for (int idx = tid; idx < 1200; idx += RT_THREADS) {
                int mb = idx / 300;
                int r  = idx % 300;                // o*30+n
                int o  = r / 30;
                const float* PR = pri + mb * 304 + r;
                const float* V  = vv  + mb * 160 + o * 16;
                float dl = 0.f;
                #pragma unroll
                for (int k = 0; k < DOUT; k++) dl = fmaf(PR[k * KSTR], V[k], dl);
                lg[idx] += dl;
            }
        }
    }

    __syncthreads();
    #pragma unroll
    for (int pass = 0; pass < 2; pass++) {
        int idx = tid + pass * RT_THREADS;         // < 640
        int mb = idx / 160;
        int j  = idx % 160;
        out[(size_t)(b0 + mb) * 160 + j] = vv[mb * 160 + j];
    }
}

// ---------------------------------------------------------------------------
extern "C" void kernel_launch(void* const* d_in, const int* in_sizes, int n_in,
                              void* d_out, int out_size) {
    const float* x  = (const float*)d_in[0];
    const float* W1 = (const float*)d_in[1];
    const float* b1 = (const float*)d_in[2];
    const float* W2 = (const float*)d_in[3];
    const float* b2 = (const float*)d_in[4];
    const float* rw = (const float*)d_in[5];
    float* out = (float*)d_out;

    (void)in_sizes; (void)n_in; (void)out_size;

    pack_kernel<<<(INDIM * NCOL + 255) / 256, 256>>>(W1, b1);
    gemm1_kernel<<<64 * 10, 256>>>(x);
    layer2_kernel<<<(Bz * NNETS) / 8, 256>>>(W2, b2);

    cudaFuncSetAttribute(routing_kernel,
                         cudaFuncAttributeMaxDynamicSharedMemorySize, RT_SMEM_BYTES);
    routing_kernel<<<Bz / 4, RT_THREADS, RT_SMEM_BYTES>>>(rw, out);
}

// round 4
// speedup vs baseline: 2.1879x; 1.7862x over previous
#include <cuda_runtime.h>
#include <cuda_bf16.h>
#include <math.h>

// Problem constants
#define Bz      8192
#define NNETS   30
#define NNODES  20
#define NOUT    10
#define DOUT    16
#define INDIM   784
#define NCOL    600          // NNETS*NNODES
#define NPAD    640

// Scratch
__device__ float g_W1p[INDIM * NPAD];
__device__ float g_b1p[NPAD];
__device__ float g_h1[Bz * NPAD];
__device__ float g_u[Bz * NCOL];

// ---------------------------------------------------------------------------
// K0: pack W1 into [784, 640] row-major, pad bias
// ---------------------------------------------------------------------------
__global__ void pack_kernel(const float* __restrict__ W1, const float* __restrict__ b1) {
    int idx = blockIdx.x * blockDim.x + threadIdx.x;
    if (idx < INDIM * NCOL) {
        int k = idx / NCOL;
        int j = idx % NCOL;
        int n = j / NNODES;
        int o = j % NNODES;
        g_W1p[k * NPAD + j] = W1[n * (INDIM * NNODES) + k * NNODES + o];
    }
    if (idx < NPAD) {
        g_b1p[idx] = (idx < NCOL) ? b1[idx] : 0.f;
    }
}

// ---------------------------------------------------------------------------
// K1: C[8192,640] = relu(A @ W1p + b1p); 128x64 tile, BK=16, register prefetch
// ---------------------------------------------------------------------------
__global__ __launch_bounds__(256) void gemm1_kernel(const float* __restrict__ A) {
    __shared__ float As[16][132];
    __shared__ float Bs[16][64];

    const int tid = threadIdx.x;
    const int bm  = blockIdx.x & 63;
    const int bn  = blockIdx.x >> 6;
    const int tx  = tid & 15;
    const int ty  = tid >> 4;

    const int arow  = tid >> 2;
    const int acol4 = (tid & 3) * 4;
    const int brow  = tid >> 4;
    const int bcol4 = (tid & 15) * 4;

    const float* Ap = A + (size_t)(bm * 128 + arow) * INDIM + acol4;
    const float* Bp = g_W1p + (size_t)brow * NPAD + bn * 64 + bcol4;

    float acc[8][4];
    #pragma unroll
    for (int i = 0; i < 8; i++)
        #pragma unroll
        for (int j = 0; j < 4; j++) acc[i][j] = 0.f;

    float4 a0 = *(const float4*)(Ap);
    float4 a1 = *(const float4*)(Ap + (size_t)64 * INDIM);
    float4 b0 = *(const float4*)(Bp);

    for (int kt = 0; kt < INDIM; kt += 16) {
        As[acol4 + 0][arow] = a0.x;
        As[acol4 + 1][arow] = a0.y;
        As[acol4 + 2][arow] = a0.z;
        As[acol4 + 3][arow] = a0.w;
        As[acol4 + 0][arow + 64] = a1.x;
        As[acol4 + 1][arow + 64] = a1.y;
        As[acol4 + 2][arow + 64] = a1.z;
        As[acol4 + 3][arow + 64] = a1.w;
        *(float4*)&Bs[brow][bcol4] = b0;
        __syncthreads();

        if (kt + 16 < INDIM) {
            a0 = *(const float4*)(Ap + kt + 16);
            a1 = *(const float4*)(Ap + (size_t)64 * INDIM + kt + 16);
            b0 = *(const float4*)(Bp + (size_t)(kt + 16) * NPAD);
        }

        #pragma unroll
        for (int k = 0; k < 16; k++) {
            float4 av0 = *(const float4*)&As[k][ty * 8];
            float4 av1 = *(const float4*)&As[k][ty * 8 + 4];
            float4 bv  = *(const float4*)&Bs[k][tx * 4];
            float a[8] = {av0.x, av0.y, av0.z, av0.w, av1.x, av1.y, av1.z, av1.w};
            float b[4] = {bv.x, bv.y, bv.z, bv.w};
            #pragma unroll
            for (int i = 0; i < 8; i++)
                #pragma unroll
                for (int j = 0; j < 4; j++)
                    acc[i][j] = fmaf(a[i], b[j], acc[i][j]);
        }
        __syncthreads();
    }

    const int colbase = bn * 64 + tx * 4;
    float4 bias = *(const float4*)&g_b1p[colbase];
    #pragma unroll
    for (int i = 0; i < 8; i++) {
        int row = bm * 128 + ty * 8 + i;
        float4 v;
        v.x = fmaxf(acc[i][0] + bias.x, 0.f);
        v.y = fmaxf(acc[i][1] + bias.y, 0.f);
        v.z = fmaxf(acc[i][2] + bias.z, 0.f);
        v.w = fmaxf(acc[i][3] + bias.w, 0.f);
        *(float4*)&g_h1[(size_t)row * NPAD + colbase] = v;
    }
}

// ---------------------------------------------------------------------------
// K2: per (b, net): h2 = relu(h1 @ W2[n] + b2[n]); u = squash(h2)
// ---------------------------------------------------------------------------
__global__ __launch_bounds__(256) void layer2_kernel(const float* __restrict__ W2,
                                                     const float* __restrict__ b2) {
    int warp = (blockIdx.x * blockDim.x + threadIdx.x) >> 5;
    int lane = threadIdx.x & 31;
    if (warp >= Bz * NNETS) return;
    int b = warp / NNETS;
    int n = warp % NNETS;

    const float* hrow = g_h1 + (size_t)b * NPAD + n * NNODES;
    float hv = (lane < NNODES) ? hrow[lane] : 0.f;

    int e = (lane < NNODES) ? lane : 0;
    const float* w = W2 + n * (NNODES * NNODES) + e;
    float acc = 0.f;
    #pragma unroll
    for (int d = 0; d < NNODES; d++) {
        float hd = __shfl_sync(0xffffffffu, hv, d);
        acc = fmaf(hd, w[d * NNODES], acc);
    }

    float h2 = 0.f;
    if (lane < NNODES) h2 = fmaxf(acc + b2[n * NNODES + lane], 0.f);

    float sq = h2 * h2;
    #pragma unroll
    for (int off = 16; off; off >>= 1) sq += __shfl_xor_sync(0xffffffffu, sq, off);

    float factor = sqrtf(sq) / (1.f + sq);
    if (lane < NNODES) g_u[(size_t)b * NCOL + n * NNODES + lane] = h2 * factor;
}

// ---------------------------------------------------------------------------
// K3 v5: MB=8 rows/block, fully vectorized (LDG.128 / LDS.128), 1 block/SM.
//   pri[mb][pair][20]  (16 used, stride-20 pad), 192000 B
//   reg2: u-staging [mb][600] ALIASED with lg2 [mb][pair][2]  (both 4800 floats)
//   pb[mb][300]
// iter0 softmax skipped (probs=0.1) -> lg2 first written in iter0 phase d.
// ---------------------------------------------------------------------------
#define RMB     8
#define PRI_F   (RMB * 300 * 20)     // 48000
#define REG2_F  (RMB * 600)          // 4800
#define PB_F    (RMB * 300)          // 2400
#define RT_SMEM_BYTES ((PRI_F + REG2_F + PB_F) * 4)   // 220800

__global__ __launch_bounds__(256, 1) void routing_kernel(const float* __restrict__ rw,
                                                         float* __restrict__ out) {
    extern __shared__ float sm[];
    float* pri  = sm;                 // [mb][pair][20]
    float* reg2 = sm + PRI_F;         // alias region
    float* pb   = reg2 + REG2_F;      // [mb][300]
    float* us   = reg2;               // [mb][600]      (live: staging..priors)
    float* lg2  = reg2;               // [mb][pair][2]  (live: iter0 d .. end)

    const int tid = threadIdx.x;
    const int b0  = blockIdx.x * RMB;

    // stage u rows (float4, coalesced)
    {
        const float4* gu = (const float4*)(g_u + (size_t)b0 * NCOL);
        for (int i = tid; i < RMB * 150; i += 256) ((float4*)us)[i] = gu[i];
    }
    __syncthreads();

    // ---- priors: thread (kq, pr) ; all 128-bit accesses ----
    {
        const int kq = tid & 3;
        const int pr = tid >> 2;                 // 0..63
        for (int g = 0; g < 5; g++) {
            int pair = pr + 64 * g;
            if (pair >= 300) break;
            int n = pair % NNETS;
            const float* rwp = rw + (size_t)pair * 320 + kq * 4;
            const float* ub  = us + n * 20;

            float acc[RMB][4];
            #pragma unroll
            for (int mb = 0; mb < RMB; mb++) {
                acc[mb][0] = 0.f; acc[mb][1] = 0.f; acc[mb][2] = 0.f; acc[mb][3] = 0.f;
            }
            #pragma unroll
            for (int dq = 0; dq < 5; dq++) {
                float4 uq[RMB];
                #pragma unroll
                for (int mb = 0; mb < RMB; mb++)
                    uq[mb] = *(const float4*)&ub[mb * 600 + dq * 4];
                #pragma unroll
                for (int j = 0; j < 4; j++) {
                    float4 w = *(const float4*)&rwp[(dq * 4 + j) * 16];
                    #pragma unroll
                    for (int mb = 0; mb < RMB; mb++) {
                        float uu = (&uq[mb].x)[j];
                        acc[mb][0] = fmaf(w.x, uu, acc[mb][0]);
                        acc[mb][1] = fmaf(w.y, uu, acc[mb][1]);
                        acc[mb][2] = fmaf(w.z, uu, acc[mb][2]);
                        acc[mb][3] = fmaf(w.w, uu, acc[mb][3]);
                    }
                }
            }
            #pragma unroll
            for (int mb = 0; mb < RMB; mb++)
                *(float4*)&pri[mb * 6000 + pair * 20 + kq * 4] =
                    make_float4(acc[mb][0], acc[mb][1], acc[mb][2], acc[mb][3]);
        }
    }
    __syncthreads();   // pri ready; us dead -> lg2 may be written

    // ---- 3 routing iterations ----
    for (int it = 0; it < 3; it++) {
        if (it > 0) {
            // softmax over o per (mb, n): 240 threads, float2 reads of lg2
            if (tid < RMB * NNETS) {
                int mb = tid / NNETS, n = tid % NNETS;
                const float* L = lg2 + mb * 600 + n * 2;
                float lo[NOUT];
                float m = -1e30f;
                #pragma unroll
                for (int o = 0; o < NOUT; o++) {
                    float2 t = *(const float2*)&L[o * 60];
                    lo[o] = t.x + t.y;
                    m = fmaxf(m, lo[o]);
                }
                float e[NOUT], ss = 0.f;
                #pragma unroll
                for (int o = 0; o < NOUT; o++) { e[o] = __expf(lo[o] - m); ss += e[o]; }
                float inv = 1.f / ss;
                float* P = pb + mb * 300 + n;
                #pragma unroll
                for (int o = 0; o < NOUT; o++) P[o * 30] = e[o] * inv;
            }
            __syncthreads();
        }

        // phases b/c/d: thread (mb, o, kh), 160 threads (5 full warps)
        if (tid < 160) {
            int kh = tid & 1, o = (tid >> 1) % NOUT, mb = tid / 20;
            const float* PR = pri + mb * 6000 + o * 600 + kh * 8;
            const float* P  = pb  + mb * 300  + o * 30;

            float s[8];
            #pragma unroll
            for (int j = 0; j < 8; j++) s[j] = 0.f;
            #pragma unroll 6
            for (int n = 0; n < NNETS; n++) {
                float p = (it == 0) ? 0.1f : P[n];
                float4 q0 = *(const float4*)&PR[n * 20];
                float4 q1 = *(const float4*)&PR[n * 20 + 4];
                s[0] = fmaf(p, q0.x, s[0]); s[1] = fmaf(p, q0.y, s[1]);
                s[2] = fmaf(p, q0.z, s[2]); s[3] = fmaf(p, q0.w, s[3]);
                s[4] = fmaf(p, q1.x, s[4]); s[5] = fmaf(p, q1.y, s[5]);
                s[6] = fmaf(p, q1.z, s[6]); s[7] = fmaf(p, q1.w, s[7]);
            }
            float sq = 0.f;
            #pragma unroll
            for (int j = 0; j < 8; j++) sq = fmaf(s[j], s[j], sq);
            sq += __shfl_xor_sync(0xffffffffu, sq, 1);
            float f = sqrtf(sq) / (1.f + sq);
            float v[8];
            #pragma unroll
            for (int j = 0; j < 8; j++) v[j] = s[j] * f;

            if (it < 2) {
                float* LG = lg2 + mb * 600 + o * 60 + kh;
                #pragma unroll 6
                for (int n = 0; n < NNETS; n++) {
                    float4 q0 = *(const float4*)&PR[n * 20];
                    float4 q1 = *(const float4*)&PR[n * 20 + 4];
                    float dl = q0.x * v[0];
                    dl = fmaf(q0.y, v[1], dl); dl = fmaf(q0.z, v[2], dl);
                    dl = fmaf(q0.w, v[3], dl); dl = fmaf(q1.x, v[4], dl);
                    dl = fmaf(q1.y, v[5], dl); dl = fmaf(q1.z, v[6], dl);
                    dl = fmaf(q1.w, v[7], dl);
                    if (it == 0) LG[n * 2] = dl;
                    else         LG[n * 2] += dl;
                }
            } else {
                float* op = out + (size_t)(b0 + mb) * 160 + o * 16 + kh * 8;
                *(float4*)op       = make_float4(v[0], v[1], v[2], v[3]);
                *(float4*)(op + 4) = make_float4(v[4], v[5], v[6], v[7]);
            }
        }
        if (it < 2) __syncthreads();   // lg2 writes visible to next softmax
    }
}

// ---------------------------------------------------------------------------
extern "C" void kernel_launch(void* const* d_in, const int* in_sizes, int n_in,
                              void* d_out, int out_size) {
    const float* x  = (const float*)d_in[0];
    const float* W1 = (const float*)d_in[1];
    const float* b1 = (const float*)d_in[2];
    const float* W2 = (const float*)d_in[3];
    const float* b2 = (const float*)d_in[4];
    const float* rw = (const float*)d_in[5];
    float* out = (float*)d_out;

    (void)in_sizes; (void)n_in; (void)out_size;

    pack_kernel<<<(INDIM * NCOL + 255) / 256, 256>>>(W1, b1);
    gemm1_kernel<<<64 * 10, 256>>>(x);
    layer2_kernel<<<(Bz * NNETS) / 8, 256>>>(W2, b2);

    cudaFuncSetAttribute(routing_kernel,
                         cudaFuncAttributeMaxDynamicSharedMemorySize, RT_SMEM_BYTES);
    routing_kernel<<<Bz / RMB, 256, RT_SMEM_BYTES>>>(rw, out);
}

// round 5
// speedup vs baseline: 2.7796x; 1.2704x over previous
#include <cuda_runtime.h>
#include <cuda_bf16.h>
#include <math.h>

// Problem constants
#define Bz      8192
#define NNETS   30
#define NNODES  20
#define NOUT    10
#define DOUT    16
#define INDIM   784
#define NCOL    600
#define NPAD    640

// Scratch
__device__ unsigned int g_xhl[Bz * INDIM];      // {bf16 hi | bf16 lo<<16} of x
__device__ unsigned int g_whl[NPAD * INDIM];    // transposed W1: [n][k] pairs
__device__ float g_b1p[NPAD];
__device__ float g_h1[Bz * NPAD];
__device__ float g_u[Bz * NCOL];

__device__ __forceinline__ unsigned int pack_hl(float x) {
    __nv_bfloat16 h = __float2bfloat16(x);
    float hf = __bfloat162float(h);
    __nv_bfloat16 l = __float2bfloat16(x - hf);
    return (unsigned int)__bfloat16_as_ushort(h) |
           ((unsigned int)__bfloat16_as_ushort(l) << 16);
}

// ---------------------------------------------------------------------------
// P0: convert x to hi/lo bf16 pairs (vectorized)
// ---------------------------------------------------------------------------
__global__ void prep_x_kernel(const float* __restrict__ x) {
    int i = blockIdx.x * blockDim.x + threadIdx.x;      // over float4s
    if (i >= (Bz * INDIM) / 4) return;
    float4 v = ((const float4*)x)[i];
    uint4 o;
    o.x = pack_hl(v.x); o.y = pack_hl(v.y); o.z = pack_hl(v.z); o.w = pack_hl(v.w);
    ((uint4*)g_xhl)[i] = o;
}

// ---------------------------------------------------------------------------
// P1: W1 [30][784][20] -> g_whl [n=640][k=784] pairs (transposed), + bias pad
// ---------------------------------------------------------------------------
__global__ void prep_w_kernel(const float* __restrict__ W1, const float* __restrict__ b1) {
    int idx = blockIdx.x * blockDim.x + threadIdx.x;
    if (idx < NPAD * INDIM) {
        int n = idx / INDIM;
        int k = idx % INDIM;
        float w = 0.f;
        if (n < NCOL) {
            int net = n / NNODES, o = n % NNODES;
            w = W1[net * (INDIM * NNODES) + k * NNODES + o];
        }
        g_whl[n * INDIM + k] = pack_hl(w);
    }
    if (idx < NPAD) g_b1p[idx] = (idx < NCOL) ? b1[idx] : 0.f;
}

// ---------------------------------------------------------------------------
// K1: tensor-core GEMM  h1 = relu(x @ W1 + b1), 3xBF16 split precision.
// Block 128x64, 8 warps (4M x 2N), warp tile 32x32, K-step 16.
// ---------------------------------------------------------------------------
#define ASTR 24   // smem row stride (elems) for 16-elem rows -> conflict-free ldmatrix

__device__ __forceinline__ void ldsm4(unsigned& r0, unsigned& r1, unsigned& r2, unsigned& r3,
                                      unsigned addr) {
    asm volatile("ldmatrix.sync.aligned.m8n8.x4.shared.b16 {%0,%1,%2,%3}, [%4];\n"
                 : "=r"(r0), "=r"(r1), "=r"(r2), "=r"(r3) : "r"(addr));
}
__device__ __forceinline__ void mma16816(float* d, const unsigned* a, const unsigned* b) {
    asm volatile(
        "mma.sync.aligned.m16n8k16.row.col.f32.bf16.bf16.f32 "
        "{%0,%1,%2,%3}, {%4,%5,%6,%7}, {%8,%9}, {%0,%1,%2,%3};\n"
        : "+f"(d[0]), "+f"(d[1]), "+f"(d[2]), "+f"(d[3])
        : "r"(a[0]), "r"(a[1]), "r"(a[2]), "r"(a[3]), "r"(b[0]), "r"(b[1]));
}

__global__ __launch_bounds__(256) void gemm1_tc_kernel() {
    __shared__ __align__(16) unsigned short Ah[128 * ASTR];
    __shared__ __align__(16) unsigned short Al[128 * ASTR];
    __shared__ __align__(16) unsigned short Bh[64 * ASTR];
    __shared__ __align__(16) unsigned short Bl[64 * ASTR];

    const int tid  = threadIdx.x;
    const int bm   = blockIdx.x & 63;      // 64 M tiles
    const int bn   = blockIdx.x >> 6;      // 10 N tiles
    const int warp = tid >> 5;
    const int lane = tid & 31;
    const int wm   = warp >> 1;            // 0..3  (M)
    const int wn   = warp & 1;             // 0..1  (N)

    // gmem staging mapping
    const int sr = tid >> 2;               // 0..63
    const int sc = tid & 3;                // 16B chunk
    const uint4* xg = (const uint4*)g_xhl;
    const uint4* wg = (const uint4*)g_whl;
    const size_t arow0 = (size_t)(bm * 128 + sr) * INDIM;
    const size_t arow1 = (size_t)(bm * 128 + 64 + sr) * INDIM;
    const size_t brow  = (size_t)(bn * 64 + sr) * INDIM;

    float acc[2][4][4];
    #pragma unroll
    for (int i = 0; i < 2; i++)
        #pragma unroll
        for (int j = 0; j < 4; j++)
            #pragma unroll
            for (int q = 0; q < 4; q++) acc[i][j][q] = 0.f;

    // ldmatrix addresses (per lane)
    const int mi = lane >> 3, lr = lane & 7;
    const int a_row = lr + ((mi & 1) << 3);
    const int a_cb  = (mi >> 1) << 4;                   // col byte offset
    const int b_row = lr + ((mi >> 1) << 3);
    const int b_cb  = (mi & 1) << 4;

    unsigned aAddrH[2], aAddrL[2], bAddrH[2], bAddrL[2];
    #pragma unroll
    for (int mt = 0; mt < 2; mt++) {
        int r = wm * 32 + mt * 16 + a_row;
        aAddrH[mt] = (unsigned)__cvta_generic_to_shared(&Ah[r * ASTR]) + a_cb;
        aAddrL[mt] = (unsigned)__cvta_generic_to_shared(&Al[r * ASTR]) + a_cb;
    }
    #pragma unroll
    for (int p = 0; p < 2; p++) {
        int r = wn * 32 + p * 16 + b_row;
        bAddrH[p] = (unsigned)__cvta_generic_to_shared(&Bh[r * ASTR]) + b_cb;
        bAddrL[p] = (unsigned)__cvta_generic_to_shared(&Bl[r * ASTR]) + b_cb;
    }

    uint4 a0r = xg[(arow0 + 0) / 4 + sc];
    uint4 a1r = xg[(arow1 + 0) / 4 + sc];
    uint4 b0r = wg[(brow  + 0) / 4 + sc];

    for (int kt = 0; kt < 49; kt++) {
        // de-interleave staged regs into smem
        {
            unsigned hi0 = (a0r.x & 0xffffu) | (a0r.y << 16);
            unsigned hi1 = (a0r.z & 0xffffu) | (a0r.w << 16);
            unsigned lo0 = (a0r.x >> 16) | (a0r.y & 0xffff0000u);
            unsigned lo1 = (a0r.z >> 16) | (a0r.w & 0xffff0000u);
            *(uint2*)&Ah[sr * ASTR + sc * 4] = make_uint2(hi0, hi1);
            *(uint2*)&Al[sr * ASTR + sc * 4] = make_uint2(lo0, lo1);
            hi0 = (a1r.x & 0xffffu) | (a1r.y << 16);
            hi1 = (a1r.z & 0xffffu) | (a1r.w << 16);
            lo0 = (a1r.x >> 16) | (a1r.y & 0xffff0000u);
            lo1 = (a1r.z >> 16) | (a1r.w & 0xffff0000u);
            *(uint2*)&Ah[(64 + sr) * ASTR + sc * 4] = make_uint2(hi0, hi1);
            *(uint2*)&Al[(64 + sr) * ASTR + sc * 4] = make_uint2(lo0, lo1);
            hi0 = (b0r.x & 0xffffu) | (b0r.y << 16);
            hi1 = (b0r.z & 0xffffu) | (b0r.w << 16);
            lo0 = (b0r.x >> 16) | (b0r.y & 0xffff0000u);
            lo1 = (b0r.z >> 16) | (b0r.w & 0xffff0000u);
            *(uint2*)&Bh[sr * ASTR + sc * 4] = make_uint2(hi0, hi1);
            *(uint2*)&Bl[sr * ASTR + sc * 4] = make_uint2(lo0, lo1);
        }
        __syncthreads();

        if (kt < 48) {
            int kb = (kt + 1) * 16;
            a0r = xg[(arow0 + kb) / 4 + sc];
            a1r = xg[(arow1 + kb) / 4 + sc];
            b0r = wg[(brow  + kb) / 4 + sc];
        }

        // fragments
        unsigned ah[2][4], al[2][4], bh[4][2], bl[4][2];
        #pragma unroll
        for (int mt = 0; mt < 2; mt++) {
            ldsm4(ah[mt][0], ah[mt][1], ah[mt][2], ah[mt][3], aAddrH[mt]);
            ldsm4(al[mt][0], al[mt][1], al[mt][2], al[mt][3], aAddrL[mt]);
        }
        #pragma unroll
        for (int p = 0; p < 2; p++) {
            ldsm4(bh[2*p][0], bh[2*p][1], bh[2*p+1][0], bh[2*p+1][1], bAddrH[p]);
            ldsm4(bl[2*p][0], bl[2*p][1], bl[2*p+1][0], bl[2*p+1][1], bAddrL[p]);
        }

        #pragma unroll
        for (int mt = 0; mt < 2; mt++)
            #pragma unroll
            for (int nt = 0; nt < 4; nt++) {
                mma16816(acc[mt][nt], ah[mt], bh[nt]);
                mma16816(acc[mt][nt], ah[mt], bl[nt]);
                mma16816(acc[mt][nt], al[mt], bh[nt]);
            }
        __syncthreads();
    }

    // epilogue: bias + relu -> g_h1
    const int g = lane >> 2, t = lane & 3;
    #pragma unroll
    for (int mt = 0; mt < 2; mt++) {
        #pragma unroll
        for (int nt = 0; nt < 4; nt++) {
            int col = bn * 64 + wn * 32 + nt * 8 + t * 2;
            float2 bias = *(const float2*)&g_b1p[col];
            int row0 = bm * 128 + wm * 32 + mt * 16 + g;
            float2 v0, v1;
            v0.x = fmaxf(acc[mt][nt][0] + bias.x, 0.f);
            v0.y = fmaxf(acc[mt][nt][1] + bias.y, 0.f);
            v1.x = fmaxf(acc[mt][nt][2] + bias.x, 0.f);
            v1.y = fmaxf(acc[mt][nt][3] + bias.y, 0.f);
            *(float2*)&g_h1[(size_t)row0 * NPAD + col]       = v0;
            *(float2*)&g_h1[(size_t)(row0 + 8) * NPAD + col] = v1;
        }
    }
}

// ---------------------------------------------------------------------------
// K2: per (b, net): h2 = relu(h1 @ W2[n] + b2[n]); u = squash(h2)
// ---------------------------------------------------------------------------
__global__ __launch_bounds__(256) void layer2_kernel(const float* __restrict__ W2,
                                                     const float* __restrict__ b2) {
    int warp = (blockIdx.x * blockDim.x + threadIdx.x) >> 5;
    int lane = threadIdx.x & 31;
    if (warp >= Bz * NNETS) return;
    int b = warp / NNETS;
    int n = warp % NNETS;

    const float* hrow = g_h1 + (size_t)b * NPAD + n * NNODES;
    float hv = (lane < NNODES) ? hrow[lane] : 0.f;

    int e = (lane < NNODES) ? lane : 0;
    const float* w = W2 + n * (NNODES * NNODES) + e;
    float acc = 0.f;
    #pragma unroll
    for (int d = 0; d < NNODES; d++) {
        float hd = __shfl_sync(0xffffffffu, hv, d);
        acc = fmaf(hd, w[d * NNODES], acc);
    }

    float h2 = 0.f;
    if (lane < NNODES) h2 = fmaxf(acc + b2[n * NNODES + lane], 0.f);

    float sq = h2 * h2;
    #pragma unroll
    for (int off = 16; off; off >>= 1) sq += __shfl_xor_sync(0xffffffffu, sq, off);

    float factor = sqrtf(sq) / (1.f + sq);
    if (lane < NNODES) g_u[(size_t)b * NCOL + n * NNODES + lane] = h2 * factor;
}

// ---------------------------------------------------------------------------
// K3 v5 (unchanged from R4): MB=8 rows/block, vectorized, 1 block/SM.
// ---------------------------------------------------------------------------
#define RMB     8
#define PRI_F   (RMB * 300 * 20)
#define REG2_F  (RMB * 600)
#define PB_F    (RMB * 300)
#define RT_SMEM_BYTES ((PRI_F + REG2_F + PB_F) * 4)

__global__ __launch_bounds__(256, 1) void routing_kernel(const float* __restrict__ rw,
                                                         float* __restrict__ out) {
    extern __shared__ float sm[];
    float* pri  = sm;
    float* reg2 = sm + PRI_F;
    float* pb   = reg2 + REG2_F;
    float* us   = reg2;
    float* lg2  = reg2;

    const int tid = threadIdx.x;
    const int b0  = blockIdx.x * RMB;

    {
        const float4* gu = (const float4*)(g_u + (size_t)b0 * NCOL);
        for (int i = tid; i < RMB * 150; i += 256) ((float4*)us)[i] = gu[i];
    }
    __syncthreads();

    {
        const int kq = tid & 3;
        const int pr = tid >> 2;
        for (int g = 0; g < 5; g++) {
            int pair = pr + 64 * g;
            if (pair >= 300) break;
            int n = pair % NNETS;
            const float* rwp = rw + (size_t)pair * 320 + kq * 4;
            const float* ub  = us + n * 20;

            float acc[RMB][4];
            #pragma unroll
            for (int mb = 0; mb < RMB; mb++) {
                acc[mb][0] = 0.f; acc[mb][1] = 0.f; acc[mb][2] = 0.f; acc[mb][3] = 0.f;
            }
            #pragma unroll
            for (int dq = 0; dq < 5; dq++) {
                float4 uq[RMB];
                #pragma unroll
                for (int mb = 0; mb < RMB; mb++)
                    uq[mb] = *(const float4*)&ub[mb * 600 + dq * 4];
                #pragma unroll
                for (int j = 0; j < 4; j++) {
                    float4 w = *(const float4*)&rwp[(dq * 4 + j) * 16];
                    #pragma unroll
                    for (int mb = 0; mb < RMB; mb++) {
                        float uu = (&uq[mb].x)[j];
                        acc[mb][0] = fmaf(w.x, uu, acc[mb][0]);
                        acc[mb][1] = fmaf(w.y, uu, acc[mb][1]);
                        acc[mb][2] = fmaf(w.z, uu, acc[mb][2]);
                        acc[mb][3] = fmaf(w.w, uu, acc[mb][3]);
                    }
                }
            }
            #pragma unroll
            for (int mb = 0; mb < RMB; mb++)
                *(float4*)&pri[mb * 6000 + pair * 20 + kq * 4] =
                    make_float4(acc[mb][0], acc[mb][1], acc[mb][2], acc[mb][3]);
        }
    }
    __syncthreads();

    for (int it = 0; it < 3; it++) {
        if (it > 0) {
            if (tid < RMB * NNETS) {
                int mb = tid / NNETS, n = tid % NNETS;
                const float* L = lg2 + mb * 600 + n * 2;
                float lo[NOUT];
                float m = -1e30f;
                #pragma unroll
                for (int o = 0; o < NOUT; o++) {
                    float2 t = *(const float2*)&L[o * 60];
                    lo[o] = t.x + t.y;
                    m = fmaxf(m, lo[o]);
                }
                float e[NOUT], ss = 0.f;
                #pragma unroll
                for (int o = 0; o < NOUT; o++) { e[o] = __expf(lo[o] - m); ss += e[o]; }
                float inv = 1.f / ss;
                float* P = pb + mb * 300 + n;
                #pragma unroll
                for (int o = 0; o < NOUT; o++) P[o * 30] = e[o] * inv;
            }
            __syncthreads();
        }

        if (tid < 160) {
            int kh = tid & 1, o = (tid >> 1) % NOUT, mb = tid / 20;
            const float* PR = pri + mb * 6000 + o * 600 + kh * 8;
            const float* P  = pb  + mb * 300  + o * 30;

            float s[8];
            #pragma unroll
            for (int j = 0; j < 8; j++) s[j] = 0.f;
            #pragma unroll 6
            for (int n = 0; n < NNETS; n++) {
                float p = (it == 0) ? 0.1f : P[n];
                float4 q0 = *(const float4*)&PR[n * 20];
                float4 q1 = *(const float4*)&PR[n * 20 + 4];
                s[0] = fmaf(p, q0.x, s[0]); s[1] = fmaf(p, q0.y, s[1]);
                s[2] = fmaf(p, q0.z, s[2]); s[3] = fmaf(p, q0.w, s[3]);
                s[4] = fmaf(p, q1.x, s[4]); s[5] = fmaf(p, q1.y, s[5]);
                s[6] = fmaf(p, q1.z, s[6]); s[7] = fmaf(p, q1.w, s[7]);
            }
            float sq = 0.f;
            #pragma unroll
            for (int j = 0; j < 8; j++) sq = fmaf(s[j], s[j], sq);
            sq += __shfl_xor_sync(0xffffffffu, sq, 1);
            float f = sqrtf(sq) / (1.f + sq);
            float v[8];
            #pragma unroll
            for (int j = 0; j < 8; j++) v[j] = s[j] * f;

            if (it < 2) {
                float* LG = lg2 + mb * 600 + o * 60 + kh;
                #pragma unroll 6
                for (int n = 0; n < NNETS; n++) {
                    float4 q0 = *(const float4*)&PR[n * 20];
                    float4 q1 = *(const float4*)&PR[n * 20 + 4];
                    float dl = q0.x * v[0];
                    dl = fmaf(q0.y, v[1], dl); dl = fmaf(q0.z, v[2], dl);
                    dl = fmaf(q0.w, v[3], dl); dl = fmaf(q1.x, v[4], dl);
                    dl = fmaf(q1.y, v[5], dl); dl = fmaf(q1.z, v[6], dl);
                    dl = fmaf(q1.w, v[7], dl);
                    if (it == 0) LG[n * 2] = dl;
                    else         LG[n * 2] += dl;
                }
            } else {
                float* op = out + (size_t)(b0 + mb) * 160 + o * 16 + kh * 8;
                *(float4*)op       = make_float4(v[0], v[1], v[2], v[3]);
                *(float4*)(op + 4) = make_float4(v[4], v[5], v[6], v[7]);
            }
        }
        if (it < 2) __syncthreads();
    }
}

// ---------------------------------------------------------------------------
extern "C" void kernel_launch(void* const* d_in, const int* in_sizes, int n_in,
                              void* d_out, int out_size) {
    const float* x  = (const float*)d_in[0];
    const float* W1 = (const float*)d_in[1];
    const float* b1 = (const float*)d_in[2];
    const float* W2 = (const float*)d_in[3];
    const float* b2 = (const float*)d_in[4];
    const float* rw = (const float*)d_in[5];
    float* out = (float*)d_out;

    (void)in_sizes; (void)n_in; (void)out_size;

    prep_x_kernel<<<(Bz * INDIM / 4 + 255) / 256, 256>>>(x);
    prep_w_kernel<<<(NPAD * INDIM + 255) / 256, 256>>>(W1, b1);
    gemm1_tc_kernel<<<64 * 10, 256>>>();
    layer2_kernel<<<(Bz * NNETS) / 8, 256>>>(W2, b2);

    cudaFuncSetAttribute(routing_kernel,
                         cudaFuncAttributeMaxDynamicSharedMemorySize, RT_SMEM_BYTES);
    routing_kernel<<<Bz / RMB, 256, RT_SMEM_BYTES>>>(rw, out);
}

// round 6
// speedup vs baseline: 2.9855x; 1.0741x over previous
#include <cuda_runtime.h>
#include <cuda_bf16.h>
#include <math.h>

// Problem constants
#define Bz      8192
#define NNETS   30
#define NNODES  20
#define NOUT    10
#define DOUT    16
#define INDIM   784
#define NCOL    600
#define NPAD    640

// Scratch
__device__ unsigned int g_xhl[Bz * INDIM];      // {bf16 hi | bf16 lo<<16} of x
__device__ unsigned int g_whl[NPAD * INDIM];    // transposed W1: [n][k] pairs
__device__ float g_b1p[NPAD];
__device__ float g_h1[Bz * NPAD];
__device__ float g_u[Bz * NCOL];

__device__ __forceinline__ unsigned int pack_hl(float x) {
    __nv_bfloat16 h = __float2bfloat16(x);
    float hf = __bfloat162float(h);
    __nv_bfloat16 l = __float2bfloat16(x - hf);
    return (unsigned int)__bfloat16_as_ushort(h) |
           ((unsigned int)__bfloat16_as_ushort(l) << 16);
}

// ---------------------------------------------------------------------------
// P0: convert x to hi/lo bf16 pairs
// ---------------------------------------------------------------------------
__global__ void prep_x_kernel(const float* __restrict__ x) {
    int i = blockIdx.x * blockDim.x + threadIdx.x;
    if (i >= (Bz * INDIM) / 4) return;
    float4 v = ((const float4*)x)[i];
    uint4 o;
    o.x = pack_hl(v.x); o.y = pack_hl(v.y); o.z = pack_hl(v.z); o.w = pack_hl(v.w);
    ((uint4*)g_xhl)[i] = o;
}

// ---------------------------------------------------------------------------
// P1: W1 [30][784][20] -> g_whl [n=640][k=784] pairs (transposed), + bias pad
// ---------------------------------------------------------------------------
__global__ void prep_w_kernel(const float* __restrict__ W1, const float* __restrict__ b1) {
    int idx = blockIdx.x * blockDim.x + threadIdx.x;
    if (idx < NPAD * INDIM) {
        int n = idx / INDIM;
        int k = idx % INDIM;
        float w = 0.f;
        if (n < NCOL) {
            int net = n / NNODES, o = n % NNODES;
            w = W1[net * (INDIM * NNODES) + k * NNODES + o];
        }
        g_whl[n * INDIM + k] = pack_hl(w);
    }
    if (idx < NPAD) g_b1p[idx] = (idx < NCOL) ? b1[idx] : 0.f;
}

// ---------------------------------------------------------------------------
// K1: tensor-core GEMM  h1 = relu(x @ W1 + b1), 3xBF16 split (unchanged R5)
// ---------------------------------------------------------------------------
#define ASTR 24

__device__ __forceinline__ void ldsm4(unsigned& r0, unsigned& r1, unsigned& r2, unsigned& r3,
                                      unsigned addr) {
    asm volatile("ldmatrix.sync.aligned.m8n8.x4.shared.b16 {%0,%1,%2,%3}, [%4];\n"
                 : "=r"(r0), "=r"(r1), "=r"(r2), "=r"(r3) : "r"(addr));
}
__device__ __forceinline__ void mma16816(float* d, const unsigned* a, const unsigned* b) {
    asm volatile(
        "mma.sync.aligned.m16n8k16.row.col.f32.bf16.bf16.f32 "
        "{%0,%1,%2,%3}, {%4,%5,%6,%7}, {%8,%9}, {%0,%1,%2,%3};\n"
        : "+f"(d[0]), "+f"(d[1]), "+f"(d[2]), "+f"(d[3])
        : "r"(a[0]), "r"(a[1]), "r"(a[2]), "r"(a[3]), "r"(b[0]), "r"(b[1]));
}

__global__ __launch_bounds__(256) void gemm1_tc_kernel() {
    __shared__ __align__(16) unsigned short Ah[128 * ASTR];
    __shared__ __align__(16) unsigned short Al[128 * ASTR];
    __shared__ __align__(16) unsigned short Bh[64 * ASTR];
    __shared__ __align__(16) unsigned short Bl[64 * ASTR];

    const int tid  = threadIdx.x;
    const int bm   = blockIdx.x & 63;
    const int bn   = blockIdx.x >> 6;
    const int warp = tid >> 5;
    const int lane = tid & 31;
    const int wm   = warp >> 1;
    const int wn   = warp & 1;

    const int sr = tid >> 2;
    const int sc = tid & 3;
    const uint4* xg = (const uint4*)g_xhl;
    const uint4* wg = (const uint4*)g_whl;
    const size_t arow0 = (size_t)(bm * 128 + sr) * INDIM;
    const size_t arow1 = (size_t)(bm * 128 + 64 + sr) * INDIM;
    const size_t brow  = (size_t)(bn * 64 + sr) * INDIM;

    float acc[2][4][4];
    #pragma unroll
    for (int i = 0; i < 2; i++)
        #pragma unroll
        for (int j = 0; j < 4; j++)
            #pragma unroll
            for (int q = 0; q < 4; q++) acc[i][j][q] = 0.f;

    const int mi = lane >> 3, lr = lane & 7;
    const int a_row = lr + ((mi & 1) << 3);
    const int a_cb  = (mi >> 1) << 4;
    const int b_row = lr + ((mi >> 1) << 3);
    const int b_cb  = (mi & 1) << 4;

    unsigned aAddrH[2], aAddrL[2], bAddrH[2], bAddrL[2];
    #pragma unroll
    for (int mt = 0; mt < 2; mt++) {
        int r = wm * 32 + mt * 16 + a_row;
        aAddrH[mt] = (unsigned)__cvta_generic_to_shared(&Ah[r * ASTR]) + a_cb;
        aAddrL[mt] = (unsigned)__cvta_generic_to_shared(&Al[r * ASTR]) + a_cb;
    }
    #pragma unroll
    for (int p = 0; p < 2; p++) {
        int r = wn * 32 + p * 16 + b_row;
        bAddrH[p] = (unsigned)__cvta_generic_to_shared(&Bh[r * ASTR]) + b_cb;
        bAddrL[p] = (unsigned)__cvta_generic_to_shared(&Bl[r * ASTR]) + b_cb;
    }

    uint4 a0r = xg[(arow0 + 0) / 4 + sc];
    uint4 a1r = xg[(arow1 + 0) / 4 + sc];
    uint4 b0r = wg[(brow  + 0) / 4 + sc];

    for (int kt = 0; kt < 49; kt++) {
        {
            unsigned hi0 = (a0r.x & 0xffffu) | (a0r.y << 16);
            unsigned hi1 = (a0r.z & 0xffffu) | (a0r.w << 16);
            unsigned lo0 = (a0r.x >> 16) | (a0r.y & 0xffff0000u);
            unsigned lo1 = (a0r.z >> 16) | (a0r.w & 0xffff0000u);
            *(uint2*)&Ah[sr * ASTR + sc * 4] = make_uint2(hi0, hi1);
            *(uint2*)&Al[sr * ASTR + sc * 4] = make_uint2(lo0, lo1);
            hi0 = (a1r.x & 0xffffu) | (a1r.y << 16);
            hi1 = (a1r.z & 0xffffu) | (a1r.w << 16);
            lo0 = (a1r.x >> 16) | (a1r.y & 0xffff0000u);
            lo1 = (a1r.z >> 16) | (a1r.w & 0xffff0000u);
            *(uint2*)&Ah[(64 + sr) * ASTR + sc * 4] = make_uint2(hi0, hi1);
            *(uint2*)&Al[(64 + sr) * ASTR + sc * 4] = make_uint2(lo0, lo1);
            hi0 = (b0r.x & 0xffffu) | (b0r.y << 16);
            hi1 = (b0r.z & 0xffffu) | (b0r.w << 16);
            lo0 = (b0r.x >> 16) | (b0r.y & 0xffff0000u);
            lo1 = (b0r.z >> 16) | (b0r.w & 0xffff0000u);
            *(uint2*)&Bh[sr * ASTR + sc * 4] = make_uint2(hi0, hi1);
            *(uint2*)&Bl[sr * ASTR + sc * 4] = make_uint2(lo0, lo1);
        }
        __syncthreads();

        if (kt < 48) {
            int kb = (kt + 1) * 16;
            a0r = xg[(arow0 + kb) / 4 + sc];
            a1r = xg[(arow1 + kb) / 4 + sc];
            b0r = wg[(brow  + kb) / 4 + sc];
        }

        unsigned ah[2][4], al[2][4], bh[4][2], bl[4][2];
        #pragma unroll
        for (int mt = 0; mt < 2; mt++) {
            ldsm4(ah[mt][0], ah[mt][1], ah[mt][2], ah[mt][3], aAddrH[mt]);
            ldsm4(al[mt][0], al[mt][1], al[mt][2], al[mt][3], aAddrL[mt]);
        }
        #pragma unroll
        for (int p = 0; p < 2; p++) {
            ldsm4(bh[2*p][0], bh[2*p][1], bh[2*p+1][0], bh[2*p+1][1], bAddrH[p]);
            ldsm4(bl[2*p][0], bl[2*p][1], bl[2*p+1][0], bl[2*p+1][1], bAddrL[p]);
        }

        #pragma unroll
        for (int mt = 0; mt < 2; mt++)
            #pragma unroll
            for (int nt = 0; nt < 4; nt++) {
                mma16816(acc[mt][nt], ah[mt], bh[nt]);
                mma16816(acc[mt][nt], ah[mt], bl[nt]);
                mma16816(acc[mt][nt], al[mt], bh[nt]);
            }
        __syncthreads();
    }

    const int g = lane >> 2, t = lane & 3;
    #pragma unroll
    for (int mt = 0; mt < 2; mt++) {
        #pragma unroll
        for (int nt = 0; nt < 4; nt++) {
            int col = bn * 64 + wn * 32 + nt * 8 + t * 2;
            float2 bias = *(const float2*)&g_b1p[col];
            int row0 = bm * 128 + wm * 32 + mt * 16 + g;
            float2 v0, v1;
            v0.x = fmaxf(acc[mt][nt][0] + bias.x, 0.f);
            v0.y = fmaxf(acc[mt][nt][1] + bias.y, 0.f);
            v1.x = fmaxf(acc[mt][nt][2] + bias.x, 0.f);
            v1.y = fmaxf(acc[mt][nt][3] + bias.y, 0.f);
            *(float2*)&g_h1[(size_t)row0 * NPAD + col]       = v0;
            *(float2*)&g_h1[(size_t)(row0 + 8) * NPAD + col] = v1;
        }
    }
}

// ---------------------------------------------------------------------------
// K2 v2: thread-per-(b,n), W2+b2 cached in smem (broadcast LDS.128), squash
// fully in-thread. Warp = 32 consecutive b at constant n.
// ---------------------------------------------------------------------------
__global__ __launch_bounds__(256) void layer2_kernel(const float* __restrict__ W2,
                                                     const float* __restrict__ b2) {
    __shared__ float W2s[NNETS * 400];   // 48000 B
    __shared__ float b2s[NCOL];

    const int tid = threadIdx.x;
    for (int i = tid; i < (NNETS * 400) / 4; i += 256)
        ((float4*)W2s)[i] = ((const float4*)W2)[i];
    for (int i = tid; i < NCOL / 4; i += 256)
        ((float4*)b2s)[i] = ((const float4*)b2)[i];
    __syncthreads();

    const int t = blockIdx.x * 256 + tid;    // t = n*Bz + b
    const int n = t >> 13;                   // /8192
    const int b = t & 8191;

    // load h (20 floats)
    float4 h4[5];
    const float4* hp = (const float4*)(g_h1 + (size_t)b * NPAD + n * NNODES);
    #pragma unroll
    for (int q = 0; q < 5; q++) h4[q] = hp[q];
    const float* h = (const float*)h4;

    // acc = bias
    float4 a4[5];
    const float4* bp = (const float4*)(b2s + n * NNODES);
    #pragma unroll
    for (int q = 0; q < 5; q++) a4[q] = bp[q];
    float* acc = (float*)a4;

    const float4* w4 = (const float4*)(W2s + n * 400);
    #pragma unroll
    for (int d = 0; d < NNODES; d++) {
        float hd = h[d];
        #pragma unroll
        for (int q = 0; q < 5; q++) {
            float4 w = w4[d * 5 + q];
            acc[q * 4 + 0] = fmaf(hd, w.x, acc[q * 4 + 0]);
            acc[q * 4 + 1] = fmaf(hd, w.y, acc[q * 4 + 1]);
            acc[q * 4 + 2] = fmaf(hd, w.z, acc[q * 4 + 2]);
            acc[q * 4 + 3] = fmaf(hd, w.w, acc[q * 4 + 3]);
        }
    }

    float sq = 0.f;
    #pragma unroll
    for (int e = 0; e < NNODES; e++) {
        acc[e] = fmaxf(acc[e], 0.f);
        sq = fmaf(acc[e], acc[e], sq);
    }
    float f = sqrtf(sq) / (1.f + sq);

    float4* up = (float4*)(g_u + (size_t)b * NCOL + n * NNODES);
    #pragma unroll
    for (int q = 0; q < 5; q++) {
        float4 o;
        o.x = acc[q * 4 + 0] * f;
        o.y = acc[q * 4 + 1] * f;
        o.z = acc[q * 4 + 2] * f;
        o.w = acc[q * 4 + 3] * f;
        up[q] = o;
    }
}

// ---------------------------------------------------------------------------
// K3 v6: 512 threads (priors phase 3 passes), MB=8 rows/block.
// ---------------------------------------------------------------------------
#define RMB     8
#define PRI_F   (RMB * 300 * 20)
#define REG2_F  (RMB * 600)
#define PB_F    (RMB * 300)
#define RT_SMEM_BYTES ((PRI_F + REG2_F + PB_F) * 4)
#define RT_THREADS 512

__global__ __launch_bounds__(RT_THREADS, 1) void routing_kernel(const float* __restrict__ rw,
                                                                float* __restrict__ out) {
    extern __shared__ float sm[];
    float* pri  = sm;
    float* reg2 = sm + PRI_F;
    float* pb   = reg2 + REG2_F;
    float* us   = reg2;
    float* lg2  = reg2;

    const int tid = threadIdx.x;
    const int b0  = blockIdx.x * RMB;

    {
        const float4* gu = (const float4*)(g_u + (size_t)b0 * NCOL);
        for (int i = tid; i < RMB * 150; i += RT_THREADS) ((float4*)us)[i] = gu[i];
    }
    __syncthreads();

    {
        const int kq = tid & 3;
        const int pr = tid >> 2;                 // 0..127
        #pragma unroll
        for (int g = 0; g < 3; g++) {
            int pair = pr + 128 * g;
            if (pair >= 300) break;
            int n = pair % NNETS;
            const float* rwp = rw + (size_t)pair * 320 + kq * 4;
            const float* ub  = us + n * 20;

            float acc[RMB][4];
            #pragma unroll
            for (int mb = 0; mb < RMB; mb++) {
                acc[mb][0] = 0.f; acc[mb][1] = 0.f; acc[mb][2] = 0.f; acc[mb][3] = 0.f;
            }
            #pragma unroll
            for (int dq = 0; dq < 5; dq++) {
                float4 uq[RMB];
                #pragma unroll
                for (int mb = 0; mb < RMB; mb++)
                    uq[mb] = *(const float4*)&ub[mb * 600 + dq * 4];
                #pragma unroll
                for (int j = 0; j < 4; j++) {
                    float4 w = *(const float4*)&rwp[(dq * 4 + j) * 16];
                    #pragma unroll
                    for (int mb = 0; mb < RMB; mb++) {
                        float uu = (&uq[mb].x)[j];
                        acc[mb][0] = fmaf(w.x, uu, acc[mb][0]);
                        acc[mb][1] = fmaf(w.y, uu, acc[mb][1]);
                        acc[mb][2] = fmaf(w.z, uu, acc[mb][2]);
                        acc[mb][3] = fmaf(w.w, uu, acc[mb][3]);
                    }
                }
            }
            #pragma unroll
            for (int mb = 0; mb < RMB; mb++)
                *(float4*)&pri[mb * 6000 + pair * 20 + kq * 4] =
                    make_float4(acc[mb][0], acc[mb][1], acc[mb][2], acc[mb][3]);
        }
    }
    __syncthreads();

    for (int it = 0; it < 3; it++) {
        if (it > 0) {
            if (tid < RMB * NNETS) {
                int mb = tid / NNETS, n = tid % NNETS;
                const float* L = lg2 + mb * 600 + n * 2;
                float lo[NOUT];
                float m = -1e30f;
                #pragma unroll
                for (int o = 0; o < NOUT; o++) {
                    float2 t = *(const float2*)&L[o * 60];
                    lo[o] = t.x + t.y;
                    m = fmaxf(m, lo[o]);
                }
                float e[NOUT], ss = 0.f;
                #pragma unroll
                for (int o = 0; o < NOUT; o++) { e[o] = __expf(lo[o] - m); ss += e[o]; }
                float inv = 1.f / ss;
                float* P = pb + mb * 300 + n;
                #pragma unroll
                for (int o = 0; o < NOUT; o++) P[o * 30] = e[o] * inv;
            }
            __syncthreads();
        }

        if (tid < 160) {
            int kh = tid & 1, o = (tid >> 1) % NOUT, mb = tid / 20;
            const float* PR = pri + mb * 6000 + o * 600 + kh * 8;
            const float* P  = pb  + mb * 300  + o * 30;

            float s[8];
            #pragma unroll
            for (int j = 0; j < 8; j++) s[j] = 0.f;
            #pragma unroll 6
            for (int n = 0; n < NNETS; n++) {
                float p = (it == 0) ? 0.1f : P[n];
                float4 q0 = *(const float4*)&PR[n * 20];
                float4 q1 = *(const float4*)&PR[n * 20 + 4];
                s[0] = fmaf(p, q0.x, s[0]); s[1] = fmaf(p, q0.y, s[1]);
                s[2] = fmaf(p, q0.z, s[2]); s[3] = fmaf(p, q0.w, s[3]);
                s[4] = fmaf(p, q1.x, s[4]); s[5] = fmaf(p, q1.y, s[5]);
                s[6] = fmaf(p, q1.z, s[6]); s[7] = fmaf(p, q1.w, s[7]);
            }
            float sq = 0.f;
            #pragma unroll
            for (int j = 0; j < 8; j++) sq = fmaf(s[j], s[j], sq);
            sq += __shfl_xor_sync(0xffffffffu, sq, 1);
            float f = sqrtf(sq) / (1.f + sq);
            float v[8];
            #pragma unroll
            for (int j = 0; j < 8; j++) v[j] = s[j] * f;

            if (it < 2) {
                float* LG = lg2 + mb * 600 + o * 60 + kh;
                #pragma unroll 6
                for (int n = 0; n < NNETS; n++) {
                    float4 q0 = *(const float4*)&PR[n * 20];
                    float4 q1 = *(const float4*)&PR[n * 20 + 4];
                    float dl = q0.x * v[0];
                    dl = fmaf(q0.y, v[1], dl); dl = fmaf(q0.z, v[2], dl);
                    dl = fmaf(q0.w, v[3], dl); dl = fmaf(q1.x, v[4], dl);
                    dl = fmaf(q1.y, v[5], dl); dl = fmaf(q1.z, v[6], dl);
                    dl = fmaf(q1.w, v[7], dl);
                    if (it == 0) LG[n * 2] = dl;
                    else         LG[n * 2] += dl;
                }
            } else {
                float* op = out + (size_t)(b0 + mb) * 160 + o * 16 + kh * 8;
                *(float4*)op       = make_float4(v[0], v[1], v[2], v[3]);
                *(float4*)(op + 4) = make_float4(v[4], v[5], v[6], v[7]);
            }
        }
        if (it < 2) __syncthreads();
    }
}

// ---------------------------------------------------------------------------
extern "C" void kernel_launch(void* const* d_in, const int* in_sizes, int n_in,
                              void* d_out, int out_size) {
    const float* x  = (const float*)d_in[0];
    const float* W1 = (const float*)d_in[1];
    const float* b1 = (const float*)d_in[2];
    const float* W2 = (const float*)d_in[3];
    const float* b2 = (const float*)d_in[4];
    const float* rw = (const float*)d_in[5];
    float* out = (float*)d_out;

    (void)in_sizes; (void)n_in; (void)out_size;

    prep_x_kernel<<<(Bz * INDIM / 4 + 255) / 256, 256>>>(x);
    prep_w_kernel<<<(NPAD * INDIM + 255) / 256, 256>>>(W1, b1);
    gemm1_tc_kernel<<<64 * 10, 256>>>();
    layer2_kernel<<<(Bz * NNETS) / 256, 256>>>(W2, b2);

    cudaFuncSetAttribute(routing_kernel,
                         cudaFuncAttributeMaxDynamicSharedMemorySize, RT_SMEM_BYTES);
    routing_kernel<<<Bz / RMB, RT_THREADS, RT_SMEM_BYTES>>>(rw, out);
}

// round 7
// speedup vs baseline: 3.3723x; 1.1296x over previous
#include <cuda_runtime.h>
#include <cuda_bf16.h>
#include <math.h>

// Problem constants
#define Bz      8192
#define NNETS   30
#define NNODES  20
#define NOUT    10
#define DOUT    16
#define INDIM   784
#define NCOL    600
#define NPAD    640

// Scratch
__device__ unsigned int g_xhl[Bz * INDIM];      // {bf16 hi | bf16 lo<<16} of x
__device__ unsigned int g_whl[NPAD * INDIM];    // transposed W1: [n][k] pairs
__device__ float g_b1p[NPAD];
__device__ float g_h1[Bz * NPAD];

__device__ __forceinline__ unsigned int pack_hl(float x) {
    __nv_bfloat16 h = __float2bfloat16(x);
    float hf = __bfloat162float(h);
    __nv_bfloat16 l = __float2bfloat16(x - hf);
    return (unsigned int)__bfloat16_as_ushort(h) |
           ((unsigned int)__bfloat16_as_ushort(l) << 16);
}

// ---------------------------------------------------------------------------
// P0: convert x to hi/lo bf16 pairs
// ---------------------------------------------------------------------------
__global__ void prep_x_kernel(const float* __restrict__ x) {
    int i = blockIdx.x * blockDim.x + threadIdx.x;
    if (i >= (Bz * INDIM) / 4) return;
    float4 v = ((const float4*)x)[i];
    uint4 o;
    o.x = pack_hl(v.x); o.y = pack_hl(v.y); o.z = pack_hl(v.z); o.w = pack_hl(v.w);
    ((uint4*)g_xhl)[i] = o;
}

// ---------------------------------------------------------------------------
// P1: W1 [30][784][20] -> g_whl [n=640][k=784] pairs (transposed), + bias pad
// ---------------------------------------------------------------------------
__global__ void prep_w_kernel(const float* __restrict__ W1, const float* __restrict__ b1) {
    int idx = blockIdx.x * blockDim.x + threadIdx.x;
    if (idx < NPAD * INDIM) {
        int n = idx / INDIM;
        int k = idx % INDIM;
        float w = 0.f;
        if (n < NCOL) {
            int net = n / NNODES, o = n % NNODES;
            w = W1[net * (INDIM * NNODES) + k * NNODES + o];
        }
        g_whl[n * INDIM + k] = pack_hl(w);
    }
    if (idx < NPAD) g_b1p[idx] = (idx < NCOL) ? b1[idx] : 0.f;
}

// ---------------------------------------------------------------------------
// K1: tensor-core GEMM  h1 = relu(x @ W1 + b1), 3xBF16 split (unchanged)
// ---------------------------------------------------------------------------
#define ASTR 24

__device__ __forceinline__ void ldsm4(unsigned& r0, unsigned& r1, unsigned& r2, unsigned& r3,
                                      unsigned addr) {
    asm volatile("ldmatrix.sync.aligned.m8n8.x4.shared.b16 {%0,%1,%2,%3}, [%4];\n"
                 : "=r"(r0), "=r"(r1), "=r"(r2), "=r"(r3) : "r"(addr));
}
__device__ __forceinline__ void mma16816(float* d, const unsigned* a, const unsigned* b) {
    asm volatile(
        "mma.sync.aligned.m16n8k16.row.col.f32.bf16.bf16.f32 "
        "{%0,%1,%2,%3}, {%4,%5,%6,%7}, {%8,%9}, {%0,%1,%2,%3};\n"
        : "+f"(d[0]), "+f"(d[1]), "+f"(d[2]), "+f"(d[3])
        : "r"(a[0]), "r"(a[1]), "r"(a[2]), "r"(a[3]), "r"(b[0]), "r"(b[1]));
}

__global__ __launch_bounds__(256) void gemm1_tc_kernel() {
    __shared__ __align__(16) unsigned short Ah[128 * ASTR];
    __shared__ __align__(16) unsigned short Al[128 * ASTR];
    __shared__ __align__(16) unsigned short Bh[64 * ASTR];
    __shared__ __align__(16) unsigned short Bl[64 * ASTR];

    const int tid  = threadIdx.x;
    const int bm   = blockIdx.x & 63;
    const int bn   = blockIdx.x >> 6;
    const int warp = tid >> 5;
    const int lane = tid & 31;
    const int wm   = warp >> 1;
    const int wn   = warp & 1;

    const int sr = tid >> 2;
    const int sc = tid & 3;
    const uint4* xg = (const uint4*)g_xhl;
    const uint4* wg = (const uint4*)g_whl;
    const size_t arow0 = (size_t)(bm * 128 + sr) * INDIM;
    const size_t arow1 = (size_t)(bm * 128 + 64 + sr) * INDIM;
    const size_t brow  = (size_t)(bn * 64 + sr) * INDIM;

    float acc[2][4][4];
    #pragma unroll
    for (int i = 0; i < 2; i++)
        #pragma unroll
        for (int j = 0; j < 4; j++)
            #pragma unroll
            for (int q = 0; q < 4; q++) acc[i][j][q] = 0.f;

    const int mi = lane >> 3, lr = lane & 7;
    const int a_row = lr + ((mi & 1) << 3);
    const int a_cb  = (mi >> 1) << 4;
    const int b_row = lr + ((mi >> 1) << 3);
    const int b_cb  = (mi & 1) << 4;

    unsigned aAddrH[2], aAddrL[2], bAddrH[2], bAddrL[2];
    #pragma unroll
    for (int mt = 0; mt < 2; mt++) {
        int r = wm * 32 + mt * 16 + a_row;
        aAddrH[mt] = (unsigned)__cvta_generic_to_shared(&Ah[r * ASTR]) + a_cb;
        aAddrL[mt] = (unsigned)__cvta_generic_to_shared(&Al[r * ASTR]) + a_cb;
    }
    #pragma unroll
    for (int p = 0; p < 2; p++) {
        int r = wn * 32 + p * 16 + b_row;
        bAddrH[p] = (unsigned)__cvta_generic_to_shared(&Bh[r * ASTR]) + b_cb;
        bAddrL[p] = (unsigned)__cvta_generic_to_shared(&Bl[r * ASTR]) + b_cb;
    }

    uint4 a0r = xg[(arow0 + 0) / 4 + sc];
    uint4 a1r = xg[(arow1 + 0) / 4 + sc];
    uint4 b0r = wg[(brow  + 0) / 4 + sc];

    for (int kt = 0; kt < 49; kt++) {
        {
            unsigned hi0 = (a0r.x & 0xffffu) | (a0r.y << 16);
            unsigned hi1 = (a0r.z & 0xffffu) | (a0r.w << 16);
            unsigned lo0 = (a0r.x >> 16) | (a0r.y & 0xffff0000u);
            unsigned lo1 = (a0r.z >> 16) | (a0r.w & 0xffff0000u);
            *(uint2*)&Ah[sr * ASTR + sc * 4] = make_uint2(hi0, hi1);
            *(uint2*)&Al[sr * ASTR + sc * 4] = make_uint2(lo0, lo1);
            hi0 = (a1r.x & 0xffffu) | (a1r.y << 16);
            hi1 = (a1r.z & 0xffffu) | (a1r.w << 16);
            lo0 = (a1r.x >> 16) | (a1r.y & 0xffff0000u);
            lo1 = (a1r.z >> 16) | (a1r.w & 0xffff0000u);
            *(uint2*)&Ah[(64 + sr) * ASTR + sc * 4] = make_uint2(hi0, hi1);
            *(uint2*)&Al[(64 + sr) * ASTR + sc * 4] = make_uint2(lo0, lo1);
            hi0 = (b0r.x & 0xffffu) | (b0r.y << 16);
            hi1 = (b0r.z & 0xffffu) | (b0r.w << 16);
            lo0 = (b0r.x >> 16) | (b0r.y & 0xffff0000u);
            lo1 = (b0r.z >> 16) | (b0r.w & 0xffff0000u);
            *(uint2*)&Bh[sr * ASTR + sc * 4] = make_uint2(hi0, hi1);
            *(uint2*)&Bl[sr * ASTR + sc * 4] = make_uint2(lo0, lo1);
        }
        __syncthreads();

        if (kt < 48) {
            int kb = (kt + 1) * 16;
            a0r = xg[(arow0 + kb) / 4 + sc];
            a1r = xg[(arow1 + kb) / 4 + sc];
            b0r = wg[(brow  + kb) / 4 + sc];
        }

        unsigned ah[2][4], al[2][4], bh[4][2], bl[4][2];
        #pragma unroll
        for (int mt = 0; mt < 2; mt++) {
            ldsm4(ah[mt][0], ah[mt][1], ah[mt][2], ah[mt][3], aAddrH[mt]);
            ldsm4(al[mt][0], al[mt][1], al[mt][2], al[mt][3], aAddrL[mt]);
        }
        #pragma unroll
        for (int p = 0; p < 2; p++) {
            ldsm4(bh[2*p][0], bh[2*p][1], bh[2*p+1][0], bh[2*p+1][1], bAddrH[p]);
            ldsm4(bl[2*p][0], bl[2*p][1], bl[2*p+1][0], bl[2*p+1][1], bAddrL[p]);
        }

        #pragma unroll
        for (int mt = 0; mt < 2; mt++)
            #pragma unroll
            for (int nt = 0; nt < 4; nt++) {
                mma16816(acc[mt][nt], ah[mt], bh[nt]);
                mma16816(acc[mt][nt], ah[mt], bl[nt]);
                mma16816(acc[mt][nt], al[mt], bh[nt]);
            }
        __syncthreads();
    }

    const int g = lane >> 2, t = lane & 3;
    #pragma unroll
    for (int mt = 0; mt < 2; mt++) {
        #pragma unroll
        for (int nt = 0; nt < 4; nt++) {
            int col = bn * 64 + wn * 32 + nt * 8 + t * 2;
            float2 bias = *(const float2*)&g_b1p[col];
            int row0 = bm * 128 + wm * 32 + mt * 16 + g;
            float2 v0, v1;
            v0.x = fmaxf(acc[mt][nt][0] + bias.x, 0.f);
            v0.y = fmaxf(acc[mt][nt][1] + bias.y, 0.f);
            v1.x = fmaxf(acc[mt][nt][2] + bias.x, 0.f);
            v1.y = fmaxf(acc[mt][nt][3] + bias.y, 0.f);
            *(float2*)&g_h1[(size_t)row0 * NPAD + col]       = v0;
            *(float2*)&g_h1[(size_t)(row0 + 8) * NPAD + col] = v1;
        }
    }
}

// ---------------------------------------------------------------------------
// K3 v7: FUSED layer2 + priors + routing. 640 threads, MB=8 rows/block.
// smem: pri[8][300][20] | reg2 (us <- later lg) | pb | vv
// Stage 1: W2+b2 staged into (dead) pri region; 240 threads compute
//          u = squash(relu(h1 @ W2 + b2)) into us.
// Stage 2: priors into pri (1200 (kq,pair) tasks over 640 threads).
// Stage 3: 3 routing iterations, phases spread over all 640 threads.
// ---------------------------------------------------------------------------
#define RMB     8
#define PRI_F   (RMB * 300 * 20)     // 48000
#define REG2_F  (RMB * 600)          // 4800
#define PB_F    (RMB * 300)          // 2400
#define VV_F    (RMB * 160)          // 1280
#define RT_SMEM_BYTES ((PRI_F + REG2_F + PB_F + VV_F) * 4)   // 225920
#define RT_THREADS 640

__global__ __launch_bounds__(RT_THREADS, 1) void routing_kernel(const float* __restrict__ W2,
                                                                const float* __restrict__ b2,
                                                                const float* __restrict__ rw,
                                                                float* __restrict__ out) {
    extern __shared__ float sm[];
    float* pri  = sm;                 // [mb][pair][20]
    float* reg2 = sm + PRI_F;
    float* pb   = reg2 + REG2_F;      // [mb][300]
    float* vv   = pb + PB_F;          // [mb][160]
    float* us   = reg2;               // [mb][600]   (live: stage1..priors)
    float* lg   = reg2;               // [mb][300]   (live: it0 phase d..end)
    float* W2s  = pri;                // [30][400]   (live: stage1 only)
    float* b2s  = pri + 12000;        // [600]

    const int tid = threadIdx.x;
    const int b0  = blockIdx.x * RMB;

    // ---- stage 1a: W2 + b2 into smem (coalesced) ----
    for (int i = tid; i < 3150; i += RT_THREADS) {
        if (i < 3000) ((float4*)W2s)[i] = ((const float4*)W2)[i];
        else          ((float4*)(pri + 12000))[i - 3000] = ((const float4*)b2)[i - 3000];
    }
    __syncthreads();

    // ---- stage 1b: u = squash(relu(h1 @ W2 + b2)) ----
    if (tid < 240) {
        const int n  = tid >> 3;           // 0..29 (groups of 8 share n)
        const int mb = tid & 7;

        float4 h4[5];
        const float4* hp = (const float4*)(g_h1 + (size_t)(b0 + mb) * NPAD + n * NNODES);
        #pragma unroll
        for (int q = 0; q < 5; q++) h4[q] = hp[q];
        const float* h = (const float*)h4;

        float4 a4[5];
        const float4* bp = (const float4*)(b2s + n * NNODES);
        #pragma unroll
        for (int q = 0; q < 5; q++) a4[q] = bp[q];
        float* acc = (float*)a4;

        const float4* w4 = (const float4*)(W2s + n * 400);
        #pragma unroll
        for (int d = 0; d < NNODES; d++) {
            float hd = h[d];
            #pragma unroll
            for (int q = 0; q < 5; q++) {
                float4 w = w4[d * 5 + q];
                acc[q * 4 + 0] = fmaf(hd, w.x, acc[q * 4 + 0]);
                acc[q * 4 + 1] = fmaf(hd, w.y, acc[q * 4 + 1]);
                acc[q * 4 + 2] = fmaf(hd, w.z, acc[q * 4 + 2]);
                acc[q * 4 + 3] = fmaf(hd, w.w, acc[q * 4 + 3]);
            }
        }
        float sq = 0.f;
        #pragma unroll
        for (int e = 0; e < NNODES; e++) {
            acc[e] = fmaxf(acc[e], 0.f);
            sq = fmaf(acc[e], acc[e], sq);
        }
        float f = sqrtf(sq) / (1.f + sq);
        float* up = us + mb * 600 + n * NNODES;
        #pragma unroll
        for (int q = 0; q < 5; q++) {
            float4 o;
            o.x = acc[q * 4 + 0] * f;
            o.y = acc[q * 4 + 1] * f;
            o.z = acc[q * 4 + 2] * f;
            o.w = acc[q * 4 + 3] * f;
            *(float4*)&up[q * 4] = o;
        }
    }
    __syncthreads();   // u ready; W2s (pri) dead

    // ---- stage 2: priors into pri ----
    #pragma unroll
    for (int g = 0; g < 2; g++) {
        int task = tid + RT_THREADS * g;
        if (task < 1200) {
            const int kq   = task & 3;
            const int pair = task >> 2;
            const int n = pair % NNETS;
            const float* rwp = rw + (size_t)pair * 320 + kq * 4;
            const float* ub  = us + n * 20;

            float acc[RMB][4];
            #pragma unroll
            for (int mb = 0; mb < RMB; mb++) {
                acc[mb][0] = 0.f; acc[mb][1] = 0.f; acc[mb][2] = 0.f; acc[mb][3] = 0.f;
            }
            #pragma unroll
            for (int dq = 0; dq < 5; dq++) {
                float4 uq[RMB];
                #pragma unroll
                for (int mb = 0; mb < RMB; mb++)
                    uq[mb] = *(const float4*)&ub[mb * 600 + dq * 4];
                #pragma unroll
                for (int j = 0; j < 4; j++) {
                    float4 w = *(const float4*)&rwp[(dq * 4 + j) * 16];
                    #pragma unroll
                    for (int mb = 0; mb < RMB; mb++) {
                        float uu = (&uq[mb].x)[j];
                        acc[mb][0] = fmaf(w.x, uu, acc[mb][0]);
                        acc[mb][1] = fmaf(w.y, uu, acc[mb][1]);
                        acc[mb][2] = fmaf(w.z, uu, acc[mb][2]);
                        acc[mb][3] = fmaf(w.w, uu, acc[mb][3]);
                    }
                }
            }
            #pragma unroll
            for (int mb = 0; mb < RMB; mb++)
                *(float4*)&pri[mb * 6000 + pair * 20 + kq * 4] =
                    make_float4(acc[mb][0], acc[mb][1], acc[mb][2], acc[mb][3]);
        }
    }
    __syncthreads();   // pri ready; us dead -> lg region free

    // ---- stage 3: routing iterations ----
    for (int it = 0; it < 3; it++) {
        if (it > 0) {
            // softmax over o per (mb, n): 240 threads
            if (tid < RMB * NNETS) {
                int mb = tid / NNETS, n = tid % NNETS;
                const float* L = lg + mb * 300 + n;
                float lo[NOUT];
                float m = -1e30f;
                #pragma unroll
                for (int o = 0; o < NOUT; o++) { lo[o] = L[o * 30]; m = fmaxf(m, lo[o]); }
                float e[NOUT], ss = 0.f;
                #pragma unroll
                for (int o = 0; o < NOUT; o++) { e[o] = __expf(lo[o] - m); ss += e[o]; }
                float inv = 1.f / ss;
                float* P = pb + mb * 300 + n;
                #pragma unroll
                for (int o = 0; o < NOUT; o++) P[o * 30] = e[o] * inv;
            }
            __syncthreads();
        }

        // phase b/c: all 640 threads: (mb, o, k-pair). squash via 3 shfls.
        {
            const int mb  = tid / 80;
            const int r   = tid % 80;
            const int o   = r >> 3;
            const int kh8 = r & 7;
            const int k0  = kh8 * 2;
            const float* PR = pri + mb * 6000 + o * 600 + k0;
            const float* P  = pb  + mb * 300  + o * 30;

            float s0 = 0.f, s1 = 0.f;
            #pragma unroll 6
            for (int n = 0; n < NNETS; n++) {
                float p = (it == 0) ? 0.1f : P[n];
                float2 q = *(const float2*)&PR[n * 20];
                s0 = fmaf(p, q.x, s0);
                s1 = fmaf(p, q.y, s1);
            }
            float sq = fmaf(s0, s0, s1 * s1);
            sq += __shfl_xor_sync(0xffffffffu, sq, 1);
            sq += __shfl_xor_sync(0xffffffffu, sq, 2);
            sq += __shfl_xor_sync(0xffffffffu, sq, 4);
            float f = sqrtf(sq) / (1.f + sq);
            float v0 = s0 * f, v1 = s1 * f;

            if (it < 2) {
                *(float2*)&vv[mb * 160 + o * 16 + k0] = make_float2(v0, v1);
            } else {
                *(float2*)&out[(size_t)(b0 + mb) * 160 + o * 16 + k0] =
                    make_float2(v0, v1);
            }
        }

        if (it < 2) {
            __syncthreads();   // vv visible
            // phase d: logits update, 2400 tasks over 640 threads
            #pragma unroll
            for (int pass = 0; pass < 4; pass++) {
                int idx = tid + pass * RT_THREADS;
                if (idx < 2400) {
                    int mb = idx / 300;
                    int r  = idx % 300;
                    int o  = r / 30;
                    const float4* PR4 = (const float4*)&pri[mb * 6000 + r * 20];
                    const float4* V4  = (const float4*)&vv[mb * 160 + o * 16];
                    float dl = 0.f;
                    #pragma unroll
                    for (int q = 0; q < 4; q++) {
                        float4 a = PR4[q];
                        float4 b = V4[q];
                        dl = fmaf(a.x, b.x, dl);
                        dl = fmaf(a.y, b.y, dl);
                        dl = fmaf(a.z, b.z, dl);
                        dl = fmaf(a.w, b.w, dl);
                    }
                    if (it == 0) lg[idx] = dl;
                    else         lg[idx] += dl;
                }
            }
            __syncthreads();   // lg visible to next softmax
        }
    }
}

// ---------------------------------------------------------------------------
extern "C" void kernel_launch(void* const* d_in, const int* in_sizes, int n_in,
                              void* d_out, int out_size) {
    const float* x  = (const float*)d_in[0];
    const float* W1 = (const float*)d_in[1];
    const float* b1 = (const float*)d_in[2];
    const float* W2 = (const float*)d_in[3];
    const float* b2 = (const float*)d_in[4];
    const float* rw = (const float*)d_in[5];
    float* out = (float*)d_out;

    (void)in_sizes; (void)n_in; (void)out_size;

    prep_x_kernel<<<(Bz * INDIM / 4 + 255) / 256, 256>>>(x);
    prep_w_kernel<<<(NPAD * INDIM + 255) / 256, 256>>>(W1, b1);
    gemm1_tc_kernel<<<64 * 10, 256>>>();

    cudaFuncSetAttribute(routing_kernel,
                         cudaFuncAttributeMaxDynamicSharedMemorySize, RT_SMEM_BYTES);
    routing_kernel<<<Bz / RMB, RT_THREADS, RT_SMEM_BYTES>>>(W2, b2, rw, out);
}

// round 8
// speedup vs baseline: 3.4119x; 1.0117x over previous
#include <cuda_runtime.h>
#include <cuda_bf16.h>
#include <math.h>

// Problem constants
#define Bz      8192
#define NNETS   30
#define NNODES  20
#define NOUT    10
#define DOUT    16
#define INDIM   784
#define NCOL    600
#define NPAD    640

// Scratch
__device__ unsigned int g_xhl[Bz * INDIM];      // {bf16 hi | bf16 lo<<16} of x
__device__ unsigned int g_whl[NPAD * INDIM];    // transposed W1: [n][k] pairs
__device__ float g_b1p[NPAD];
__device__ float g_h1[Bz * NPAD];

__device__ __forceinline__ unsigned int pack_hl(float x) {
    __nv_bfloat16 h = __float2bfloat16(x);
    float hf = __bfloat162float(h);
    __nv_bfloat16 l = __float2bfloat16(x - hf);
    return (unsigned int)__bfloat16_as_ushort(h) |
           ((unsigned int)__bfloat16_as_ushort(l) << 16);
}

// ---------------------------------------------------------------------------
// P0: convert x to hi/lo bf16 pairs
// ---------------------------------------------------------------------------
__global__ void prep_x_kernel(const float* __restrict__ x) {
    int i = blockIdx.x * blockDim.x + threadIdx.x;
    if (i >= (Bz * INDIM) / 4) return;
    float4 v = ((const float4*)x)[i];
    uint4 o;
    o.x = pack_hl(v.x); o.y = pack_hl(v.y); o.z = pack_hl(v.z); o.w = pack_hl(v.w);
    ((uint4*)g_xhl)[i] = o;
}

// ---------------------------------------------------------------------------
// P1: W1 [30][784][20] -> g_whl [n=640][k=784] pairs (transposed), + bias pad
// ---------------------------------------------------------------------------
__global__ void prep_w_kernel(const float* __restrict__ W1, const float* __restrict__ b1) {
    int idx = blockIdx.x * blockDim.x + threadIdx.x;
    if (idx < NPAD * INDIM) {
        int n = idx / INDIM;
        int k = idx % INDIM;
        float w = 0.f;
        if (n < NCOL) {
            int net = n / NNODES, o = n % NNODES;
            w = W1[net * (INDIM * NNODES) + k * NNODES + o];
        }
        g_whl[n * INDIM + k] = pack_hl(w);
    }
    if (idx < NPAD) g_b1p[idx] = (idx < NCOL) ? b1[idx] : 0.f;
}

// ---------------------------------------------------------------------------
// K1: tensor-core GEMM  h1 = relu(x @ W1 + b1), 3xBF16 split,
// DOUBLE-BUFFERED smem (one barrier per k-step).
// ---------------------------------------------------------------------------
#define ASTR 24
#define A_BUF_B (128 * ASTR * 2)    // bytes per A buffer
#define B_BUF_B (64 * ASTR * 2)     // bytes per B buffer

__device__ __forceinline__ void ldsm4(unsigned& r0, unsigned& r1, unsigned& r2, unsigned& r3,
                                      unsigned addr) {
    asm volatile("ldmatrix.sync.aligned.m8n8.x4.shared.b16 {%0,%1,%2,%3}, [%4];\n"
                 : "=r"(r0), "=r"(r1), "=r"(r2), "=r"(r3) : "r"(addr));
}
__device__ __forceinline__ void mma16816(float* d, const unsigned* a, const unsigned* b) {
    asm volatile(
        "mma.sync.aligned.m16n8k16.row.col.f32.bf16.bf16.f32 "
        "{%0,%1,%2,%3}, {%4,%5,%6,%7}, {%8,%9}, {%0,%1,%2,%3};\n"
        : "+f"(d[0]), "+f"(d[1]), "+f"(d[2]), "+f"(d[3])
        : "r"(a[0]), "r"(a[1]), "r"(a[2]), "r"(a[3]), "r"(b[0]), "r"(b[1]));
}

__global__ __launch_bounds__(256) void gemm1_tc_kernel() {
    __shared__ __align__(16) unsigned short Ah[2][128 * ASTR];
    __shared__ __align__(16) unsigned short Al[2][128 * ASTR];
    __shared__ __align__(16) unsigned short Bh[2][64 * ASTR];
    __shared__ __align__(16) unsigned short Bl[2][64 * ASTR];

    const int tid  = threadIdx.x;
    const int bm   = blockIdx.x & 63;
    const int bn   = blockIdx.x >> 6;
    const int warp = tid >> 5;
    const int lane = tid & 31;
    const int wm   = warp >> 1;
    const int wn   = warp & 1;

    const int sr = tid >> 2;
    const int sc = tid & 3;
    const uint4* xg = (const uint4*)g_xhl;
    const uint4* wg = (const uint4*)g_whl;
    const size_t arow0 = (size_t)(bm * 128 + sr) * INDIM;
    const size_t arow1 = (size_t)(bm * 128 + 64 + sr) * INDIM;
    const size_t brow  = (size_t)(bn * 64 + sr) * INDIM;

    float acc[2][4][4];
    #pragma unroll
    for (int i = 0; i < 2; i++)
        #pragma unroll
        for (int j = 0; j < 4; j++)
            #pragma unroll
            for (int q = 0; q < 4; q++) acc[i][j][q] = 0.f;

    const int mi = lane >> 3, lr = lane & 7;
    const int a_row = lr + ((mi & 1) << 3);
    const int a_cb  = (mi >> 1) << 4;
    const int b_row = lr + ((mi >> 1) << 3);
    const int b_cb  = (mi & 1) << 4;

    unsigned aAddrH0[2], aAddrL0[2], bAddrH0[2], bAddrL0[2];
    #pragma unroll
    for (int mt = 0; mt < 2; mt++) {
        int r = wm * 32 + mt * 16 + a_row;
        aAddrH0[mt] = (unsigned)__cvta_generic_to_shared(&Ah[0][r * ASTR]) + a_cb;
        aAddrL0[mt] = (unsigned)__cvta_generic_to_shared(&Al[0][r * ASTR]) + a_cb;
    }
    #pragma unroll
    for (int p = 0; p < 2; p++) {
        int r = wn * 32 + p * 16 + b_row;
        bAddrH0[p] = (unsigned)__cvta_generic_to_shared(&Bh[0][r * ASTR]) + b_cb;
        bAddrL0[p] = (unsigned)__cvta_generic_to_shared(&Bl[0][r * ASTR]) + b_cb;
    }

    uint4 a0r = xg[arow0 / 4 + sc];
    uint4 a1r = xg[arow1 / 4 + sc];
    uint4 b0r = wg[brow  / 4 + sc];

    // store tile 0 into buffer 0
    {
        unsigned short* AhP = Ah[0]; unsigned short* AlP = Al[0];
        unsigned short* BhP = Bh[0]; unsigned short* BlP = Bl[0];
        unsigned hi0 = (a0r.x & 0xffffu) | (a0r.y << 16);
        unsigned hi1 = (a0r.z & 0xffffu) | (a0r.w << 16);
        unsigned lo0 = (a0r.x >> 16) | (a0r.y & 0xffff0000u);
        unsigned lo1 = (a0r.z >> 16) | (a0r.w & 0xffff0000u);
        *(uint2*)&AhP[sr * ASTR + sc * 4] = make_uint2(hi0, hi1);
        *(uint2*)&AlP[sr * ASTR + sc * 4] = make_uint2(lo0, lo1);
        hi0 = (a1r.x & 0xffffu) | (a1r.y << 16);
        hi1 = (a1r.z & 0xffffu) | (a1r.w << 16);
        lo0 = (a1r.x >> 16) | (a1r.y & 0xffff0000u);
        lo1 = (a1r.z >> 16) | (a1r.w & 0xffff0000u);
        *(uint2*)&AhP[(64 + sr) * ASTR + sc * 4] = make_uint2(hi0, hi1);
        *(uint2*)&AlP[(64 + sr) * ASTR + sc * 4] = make_uint2(lo0, lo1);
        hi0 = (b0r.x & 0xffffu) | (b0r.y << 16);
        hi1 = (b0r.z & 0xffffu) | (b0r.w << 16);
        lo0 = (b0r.x >> 16) | (b0r.y & 0xffff0000u);
        lo1 = (b0r.z >> 16) | (b0r.w & 0xffff0000u);
        *(uint2*)&BhP[sr * ASTR + sc * 4] = make_uint2(hi0, hi1);
        *(uint2*)&BlP[sr * ASTR + sc * 4] = make_uint2(lo0, lo1);
    }
    __syncthreads();

    for (int kt = 0; kt < 49; kt++) {
        const int cur = kt & 1;
        const unsigned aOff = cur ? A_BUF_B : 0;
        const unsigned bOff = cur ? B_BUF_B : 0;

        if (kt < 48) {
            int kb = (kt + 1) * 16;
            a0r = xg[(arow0 + kb) / 4 + sc];
            a1r = xg[(arow1 + kb) / 4 + sc];
            b0r = wg[(brow  + kb) / 4 + sc];
        }

        unsigned ah[2][4], al[2][4], bh[4][2], bl[4][2];
        #pragma unroll
        for (int mt = 0; mt < 2; mt++) {
            ldsm4(ah[mt][0], ah[mt][1], ah[mt][2], ah[mt][3], aAddrH0[mt] + aOff);
            ldsm4(al[mt][0], al[mt][1], al[mt][2], al[mt][3], aAddrL0[mt] + aOff);
        }
        #pragma unroll
        for (int p = 0; p < 2; p++) {
            ldsm4(bh[2*p][0], bh[2*p][1], bh[2*p+1][0], bh[2*p+1][1], bAddrH0[p] + bOff);
            ldsm4(bl[2*p][0], bl[2*p][1], bl[2*p+1][0], bl[2*p+1][1], bAddrL0[p] + bOff);
        }

        #pragma unroll
        for (int mt = 0; mt < 2; mt++)
            #pragma unroll
            for (int nt = 0; nt < 4; nt++) {
                mma16816(acc[mt][nt], ah[mt], bh[nt]);
                mma16816(acc[mt][nt], ah[mt], bl[nt]);
                mma16816(acc[mt][nt], al[mt], bh[nt]);
            }

        if (kt < 48) {
            const int nxt = (kt + 1) & 1;
            unsigned short* AhP = Ah[nxt]; unsigned short* AlP = Al[nxt];
            unsigned short* BhP = Bh[nxt]; unsigned short* BlP = Bl[nxt];
            unsigned hi0 = (a0r.x & 0xffffu) | (a0r.y << 16);
            unsigned hi1 = (a0r.z & 0xffffu) | (a0r.w << 16);
            unsigned lo0 = (a0r.x >> 16) | (a0r.y & 0xffff0000u);
            unsigned lo1 = (a0r.z >> 16) | (a0r.w & 0xffff0000u);
            *(uint2*)&AhP[sr * ASTR + sc * 4] = make_uint2(hi0, hi1);
            *(uint2*)&AlP[sr * ASTR + sc * 4] = make_uint2(lo0, lo1);
            hi0 = (a1r.x & 0xffffu) | (a1r.y << 16);
            hi1 = (a1r.z & 0xffffu) | (a1r.w << 16);
            lo0 = (a1r.x >> 16) | (a1r.y & 0xffff0000u);
            lo1 = (a1r.z >> 16) | (a1r.w & 0xffff0000u);
            *(uint2*)&AhP[(64 + sr) * ASTR + sc * 4] = make_uint2(hi0, hi1);
            *(uint2*)&AlP[(64 + sr) * ASTR + sc * 4] = make_uint2(lo0, lo1);
            hi0 = (b0r.x & 0xffffu) | (b0r.y << 16);
            hi1 = (b0r.z & 0xffffu) | (b0r.w << 16);
            lo0 = (b0r.x >> 16) | (b0r.y & 0xffff0000u);
            lo1 = (b0r.z >> 16) | (b0r.w & 0xffff0000u);
            *(uint2*)&BhP[sr * ASTR + sc * 4] = make_uint2(hi0, hi1);
            *(uint2*)&BlP[sr * ASTR + sc * 4] = make_uint2(lo0, lo1);
        }
        __syncthreads();
    }

    const int g = lane >> 2, t = lane & 3;
    #pragma unroll
    for (int mt = 0; mt < 2; mt++) {
        #pragma unroll
        for (int nt = 0; nt < 4; nt++) {
            int col = bn * 64 + wn * 32 + nt * 8 + t * 2;
            float2 bias = *(const float2*)&g_b1p[col];
            int row0 = bm * 128 + wm * 32 + mt * 16 + g;
            float2 v0, v1;
            v0.x = fmaxf(acc[mt][nt][0] + bias.x, 0.f);
            v0.y = fmaxf(acc[mt][nt][1] + bias.y, 0.f);
            v1.x = fmaxf(acc[mt][nt][2] + bias.x, 0.f);
            v1.y = fmaxf(acc[mt][nt][3] + bias.y, 0.f);
            *(float2*)&g_h1[(size_t)row0 * NPAD + col]       = v0;
            *(float2*)&g_h1[(size_t)(row0 + 8) * NPAD + col] = v1;
        }
    }
}

// ---------------------------------------------------------------------------
// K3 v8: FUSED layer2 + priors + routing. 768 threads, MB=8 rows/block.
// Stage-2 loop reordered (w outer, mb inner) to cap register pressure.
// ---------------------------------------------------------------------------
#define RMB     8
#define PRI_F   (RMB * 300 * 20)     // 48000
#define REG2_F  (RMB * 600)          // 4800
#define PB_F    (RMB * 300)          // 2400
#define VV_F    (RMB * 160)          // 1280
#define RT_SMEM_BYTES ((PRI_F + REG2_F + PB_F + VV_F) * 4)   // 225920
#define RT_THREADS 768

__global__ __launch_bounds__(RT_THREADS, 1) void routing_kernel(const float* __restrict__ W2,
                                                                const float* __restrict__ b2,
                                                                const float* __restrict__ rw,
                                                                float* __restrict__ out) {
    extern __shared__ float sm[];
    float* pri  = sm;                 // [mb][pair][20]
    float* reg2 = sm + PRI_F;
    float* pb   = reg2 + REG2_F;      // [mb][300]
    float* vv   = pb + PB_F;          // [mb][160]
    float* us   = reg2;               // [mb][600]   (live: stage1..priors)
    float* lg   = reg2;               // [mb][300]   (live: it0 phase d..end)
    float* W2s  = pri;                // [30][400]   (live: stage1 only)
    float* b2s  = pri + 12000;        // [600]

    const int tid = threadIdx.x;
    const int b0  = blockIdx.x * RMB;

    // ---- stage 1a: W2 + b2 into smem (coalesced) ----
    for (int i = tid; i < 3150; i += RT_THREADS) {
        if (i < 3000) ((float4*)W2s)[i] = ((const float4*)W2)[i];
        else          ((float4*)(pri + 12000))[i - 3000] = ((const float4*)b2)[i - 3000];
    }
    __syncthreads();

    // ---- stage 1b: u = squash(relu(h1 @ W2 + b2)) ----
    if (tid < 240) {
        const int n  = tid >> 3;
        const int mb = tid & 7;

        float4 h4[5];
        const float4* hp = (const float4*)(g_h1 + (size_t)(b0 + mb) * NPAD + n * NNODES);
        #pragma unroll
        for (int q = 0; q < 5; q++) h4[q] = hp[q];
        const float* h = (const float*)h4;

        float4 a4[5];
        const float4* bp = (const float4*)(b2s + n * NNODES);
        #pragma unroll
        for (int q = 0; q < 5; q++) a4[q] = bp[q];
        float* acc = (float*)a4;

        const float4* w4 = (const float4*)(W2s + n * 400);
        #pragma unroll
        for (int d = 0; d < NNODES; d++) {
            float hd = h[d];
            #pragma unroll
            for (int q = 0; q < 5; q++) {
                float4 w = w4[d * 5 + q];
                acc[q * 4 + 0] = fmaf(hd, w.x, acc[q * 4 + 0]);
                acc[q * 4 + 1] = fmaf(hd, w.y, acc[q * 4 + 1]);
                acc[q * 4 + 2] = fmaf(hd, w.z, acc[q * 4 + 2]);
                acc[q * 4 + 3] = fmaf(hd, w.w, acc[q * 4 + 3]);
            }
        }
        float sq = 0.f;
        #pragma unroll
        for (int e = 0; e < NNODES; e++) {
            acc[e] = fmaxf(acc[e], 0.f);
            sq = fmaf(acc[e], acc[e], sq);
        }
        float f = sqrtf(sq) / (1.f + sq);
        float* up = us + mb * 600 + n * NNODES;
        #pragma unroll
        for (int q = 0; q < 5; q++) {
            float4 o;
            o.x = acc[q * 4 + 0] * f;
            o.y = acc[q * 4 + 1] * f;
            o.z = acc[q * 4 + 2] * f;
            o.w = acc[q * 4 + 3] * f;
            *(float4*)&up[q * 4] = o;
        }
    }
    __syncthreads();   // u ready; W2s (pri) dead

    // ---- stage 2: priors into pri (reordered loops: low reg pressure) ----
    #pragma unroll
    for (int g = 0; g < 2; g++) {
        int task = tid + RT_THREADS * g;
        if (task < 1200) {
            const int kq   = task & 3;
            const int pair = task >> 2;
            const int n = pair % NNETS;
            const float* rwp = rw + (size_t)pair * 320 + kq * 4;
            const float* ub  = us + n * 20;

            float acc[RMB][4];
            #pragma unroll
            for (int mb = 0; mb < RMB; mb++) {
                acc[mb][0] = 0.f; acc[mb][1] = 0.f; acc[mb][2] = 0.f; acc[mb][3] = 0.f;
            }
            #pragma unroll
            for (int dq = 0; dq < 5; dq++) {
                float4 w0 = *(const float4*)&rwp[(dq * 4 + 0) * 16];
                float4 w1 = *(const float4*)&rwp[(dq * 4 + 1) * 16];
                float4 w2 = *(const float4*)&rwp[(dq * 4 + 2) * 16];
                float4 w3 = *(const float4*)&rwp[(dq * 4 + 3) * 16];
                #pragma unroll
                for (int mb = 0; mb < RMB; mb++) {
                    float4 uq = *(const float4*)&ub[mb * 600 + dq * 4];
                    acc[mb][0] = fmaf(w0.x, uq.x, acc[mb][0]);
                    acc[mb][1] = fmaf(w0.y, uq.x, acc[mb][1]);
                    acc[mb][2] = fmaf(w0.z, uq.x, acc[mb][2]);
                    acc[mb][3] = fmaf(w0.w, uq.x, acc[mb][3]);
                    acc[mb][0] = fmaf(w1.x, uq.y, acc[mb][0]);
                    acc[mb][1] = fmaf(w1.y, uq.y, acc[mb][1]);
                    acc[mb][2] = fmaf(w1.z, uq.y, acc[mb][2]);
                    acc[mb][3] = fmaf(w1.w, uq.y, acc[mb][3]);
                    acc[mb][0] = fmaf(w2.x, uq.z, acc[mb][0]);
                    acc[mb][1] = fmaf(w2.y, uq.z, acc[mb][1]);
                    acc[mb][2] = fmaf(w2.z, uq.z, acc[mb][2]);
                    acc[mb][3] = fmaf(w2.w, uq.z, acc[mb][3]);
                    acc[mb][0] = fmaf(w3.x, uq.w, acc[mb][0]);
                    acc[mb][1] = fmaf(w3.y, uq.w, acc[mb][1]);
                    acc[mb][2] = fmaf(w3.z, uq.w, acc[mb][2]);
                    acc[mb][3] = fmaf(w3.w, uq.w, acc[mb][3]);
                }
            }
            #pragma unroll
            for (int mb = 0; mb < RMB; mb++)
                *(float4*)&pri[mb * 6000 + pair * 20 + kq * 4] =
                    make_float4(acc[mb][0], acc[mb][1], acc[mb][2], acc[mb][3]);
        }
    }
    __syncthreads();   // pri ready; us dead -> lg region free

    // ---- stage 3: routing iterations ----
    for (int it = 0; it < 3; it++) {
        if (it > 0) {
            if (tid < RMB * NNETS) {
                int mb = tid / NNETS, n = tid % NNETS;
                const float* L = lg + mb * 300 + n;
                float lo[NOUT];
                float m = -1e30f;
                #pragma unroll
                for (int o = 0; o < NOUT; o++) { lo[o] = L[o * 30]; m = fmaxf(m, lo[o]); }
                float e[NOUT], ss = 0.f;
                #pragma unroll
                for (int o = 0; o < NOUT; o++) { e[o] = __expf(lo[o] - m); ss += e[o]; }
                float inv = 1.f / ss;
                float* P = pb + mb * 300 + n;
                #pragma unroll
                for (int o = 0; o < NOUT; o++) P[o * 30] = e[o] * inv;
            }
            __syncthreads();
        }

        // phase b/c: 640 threads: (mb, o, k-pair). squash via 3 shfls.
        if (tid < 640) {
            const int mb  = tid / 80;
            const int r   = tid % 80;
            const int o   = r >> 3;
            const int kh8 = r & 7;
            const int k0  = kh8 * 2;
            const float* PR = pri + mb * 6000 + o * 600 + k0;
            const float* P  = pb  + mb * 300  + o * 30;

            float s0 = 0.f, s1 = 0.f;
            #pragma unroll 6
            for (int n = 0; n < NNETS; n++) {
                float p = (it == 0) ? 0.1f : P[n];
                float2 q = *(const float2*)&PR[n * 20];
                s0 = fmaf(p, q.x, s0);
                s1 = fmaf(p, q.y, s1);
            }
            float sq = fmaf(s0, s0, s1 * s1);
            sq += __shfl_xor_sync(0xffffffffu, sq, 1);
            sq += __shfl_xor_sync(0xffffffffu, sq, 2);
            sq += __shfl_xor_sync(0xffffffffu, sq, 4);
            float f = sqrtf(sq) / (1.f + sq);
            float v0 = s0 * f, v1 = s1 * f;

            if (it < 2) {
                *(float2*)&vv[mb * 160 + o * 16 + k0] = make_float2(v0, v1);
            } else {
                *(float2*)&out[(size_t)(b0 + mb) * 160 + o * 16 + k0] =
                    make_float2(v0, v1);
            }
        }

        if (it < 2) {
            __syncthreads();
            // phase d: logits update, 2400 tasks over 768 threads
            #pragma unroll
            for (int pass = 0; pass < 4; pass++) {
                int idx = tid + pass * RT_THREADS;
                if (idx < 2400) {
                    int mb = idx / 300;
                    int r  = idx % 300;
                    int o  = r / 30;
                    const float4* PR4 = (const float4*)&pri[mb * 6000 + r * 20];
                    const float4* V4  = (const float4*)&vv[mb * 160 + o * 16];
                    float dl = 0.f;
                    #pragma unroll
                    for (int q = 0; q < 4; q++) {
                        float4 a = PR4[q];
                        float4 b = V4[q];
                        dl = fmaf(a.x, b.x, dl);
                        dl = fmaf(a.y, b.y, dl);
                        dl = fmaf(a.z, b.z, dl);
                        dl = fmaf(a.w, b.w, dl);
                    }
                    if (it == 0) lg[idx] = dl;
                    else         lg[idx] += dl;
                }
            }
            __syncthreads();
        }
    }
}

// ---------------------------------------------------------------------------
extern "C" void kernel_launch(void* const* d_in, const int* in_sizes, int n_in,
                              void* d_out, int out_size) {
    const float* x  = (const float*)d_in[0];
    const float* W1 = (const float*)d_in[1];
    const float* b1 = (const float*)d_in[2];
    const float* W2 = (const float*)d_in[3];
    const float* b2 = (const float*)d_in[4];
    const float* rw = (const float*)d_in[5];
    float* out = (float*)d_out;

    (void)in_sizes; (void)n_in; (void)out_size;

    prep_x_kernel<<<(Bz * INDIM / 4 + 255) / 256, 256>>>(x);
    prep_w_kernel<<<(NPAD * INDIM + 255) / 256, 256>>>(W1, b1);
    gemm1_tc_kernel<<<64 * 10, 256>>>();

    cudaFuncSetAttribute(routing_kernel,
                         cudaFuncAttributeMaxDynamicSharedMemorySize, RT_SMEM_BYTES);
    routing_kernel<<<Bz / RMB, RT_THREADS, RT_SMEM_BYTES>>>(W2, b2, rw, out);
}